// round 13
// baseline (speedup 1.0000x reference)
#include <cuda_runtime.h>
#include <math.h>
#include <stdint.h>

// Problem constants
#define BB      16
#define LL      2048
#define DD      768
#define HH      12
#define NLAYER  4
#define FDIM    32
#define HDIM    64
#define NTOK    (BB * LL)            // 32768
#define ATTN_EPS 1e-6f
#define LN_EPS   1e-5f
#define NBH     (BB * HH)            // 192
#define KVCH    4                    // kv L-split chunks

// ---------------------------------------------------------------------------
// Scratch buffers
// ---------------------------------------------------------------------------
__device__ float g_X [(size_t)NTOK * DD];
__device__ float g_Y [(size_t)NTOK * DD];
__device__ float g_Q [(size_t)NTOK * DD];
__device__ float g_V [(size_t)NTOK * DD];
__device__ float g_PHK[(size_t)NTOK * HH * FDIM];
__device__ float g_KV  [NBH * FDIM * HDIM];
__device__ float g_KSUM[NBH * FDIM];
__device__ float g_KVP [KVCH * NBH * FDIM * HDIM];
__device__ float g_KSP [KVCH * NBH * FDIM];
__device__ float g_COS [LL * (HDIM / 2)];
__device__ float g_SIN [LL * (HDIM / 2)];

// ---------------------------------------------------------------------------
// PTX helpers
// ---------------------------------------------------------------------------
__device__ __forceinline__ void cpa16(uint32_t d, const void* s) {
    asm volatile("cp.async.cg.shared.global [%0], [%1], 16;" :: "r"(d), "l"(s));
}
#define CPA_COMMIT() asm volatile("cp.async.commit_group;" ::: "memory")
#define CPA_WAIT1()  asm volatile("cp.async.wait_group 1;" ::: "memory")

__device__ __forceinline__ uint32_t smem_u32(const void* p) {
    uint32_t a;
    asm("{ .reg .u64 t; cvta.to.shared.u64 t, %1; cvt.u32.u64 %0, t; }"
        : "=r"(a) : "l"(p));
    return a;
}

__device__ __forceinline__ float tf32_rna(float x) {
    unsigned r;
    asm("cvt.rna.tf32.f32 %0, %1;" : "=r"(r) : "f"(x));
    return __uint_as_float(r);
}

__device__ __forceinline__ void mma_tf32(float* c, const unsigned* a, const unsigned* b) {
    asm volatile(
        "mma.sync.aligned.m16n8k8.row.col.f32.tf32.tf32.f32 "
        "{%0,%1,%2,%3},{%4,%5,%6,%7},{%8,%9},{%0,%1,%2,%3};"
        : "+f"(c[0]), "+f"(c[1]), "+f"(c[2]), "+f"(c[3])
        : "r"(a[0]), "r"(a[1]), "r"(a[2]), "r"(a[3]), "r"(b[0]), "r"(b[1]));
}

// ---------------------------------------------------------------------------
// GEMM config (R4-proven shape): 128x128x32 tile, 8 warps of 64x32,
// cp.async 3-stage.
// ---------------------------------------------------------------------------
#define TM 128
#define TN 128
#define TBK 32
#define NST 3
#define A_STR 36
#define B_STR 136
#define A_TILE_B (TM * A_STR * 4)           // 18432
#define B_TILE_B (TBK * B_STR * 4)          // 17408
#define STAGE_B  (A_TILE_B + B_TILE_B)      // 35840
#define OFF_BIAS (NST * STAGE_B)            // 107520
#define SMEM_GEMM (OFF_BIAS + TN * 4)       // 108032
#define NKT (DD / TBK)                      // 24

// Mainloop macro body (acc must be declared by caller)
#define GEMM_MAINLOOP(A_, W_, row0_, col0_)                                   \
    int ar = tid >> 3, akc = tid & 7;                                         \
    int bk = tid >> 5, bnc = tid & 31;                                        \
    auto load_stage = [&](int u) {                                            \
        uint32_t st = sb + (u % NST) * STAGE_B;                               \
        int k0 = u * TBK;                                                     \
        _Pragma("unroll")                                                     \
        for (int i = 0; i < 4; i++) {                                         \
            int r = ar + i * 32;                                              \
            cpa16(st + r * (A_STR * 4) + akc * 16,                            \
                  A_ + (row0_ + r) * DD + k0 + akc * 4);                      \
        }                                                                     \
        uint32_t bbase = st + A_TILE_B;                                       \
        _Pragma("unroll")                                                     \
        for (int i = 0; i < 4; i++) {                                         \
            int k = bk + i * 8;                                               \
            cpa16(bbase + k * (B_STR * 4) + bnc * 16,                         \
                  W_ + (size_t)(k0 + k) * DD + col0_ + bnc * 4);              \
        }                                                                     \
    };                                                                        \
    load_stage(0); CPA_COMMIT();                                              \
    load_stage(1); CPA_COMMIT();                                              \
    for (int t = 0; t < NKT; t++) {                                           \
        CPA_WAIT1();                                                          \
        __syncthreads();                                                      \
        if (t + 2 < NKT) load_stage(t + 2);                                   \
        CPA_COMMIT();                                                         \
        const float* sA = (const float*)(smem + (t % NST) * STAGE_B);         \
        const float* sB = (const float*)(smem + (t % NST) * STAGE_B + A_TILE_B); \
        _Pragma("unroll")                                                     \
        for (int ks = 0; ks < 4; ks++) {                                      \
            int kc = ks * 8 + (lane & 3);                                     \
            unsigned a[4][4], b[4][2];                                        \
            _Pragma("unroll")                                                 \
            for (int fm = 0; fm < 4; fm++) {                                  \
                int r = wm + fm * 16 + (lane >> 2);                           \
                a[fm][0] = __float_as_uint(sA[r * A_STR + kc]);               \
                a[fm][1] = __float_as_uint(sA[(r + 8) * A_STR + kc]);         \
                a[fm][2] = __float_as_uint(sA[r * A_STR + kc + 4]);           \
                a[fm][3] = __float_as_uint(sA[(r + 8) * A_STR + kc + 4]);     \
            }                                                                 \
            _Pragma("unroll")                                                 \
            for (int fn = 0; fn < 4; fn++) {                                  \
                int cn = wn + fn * 8 + (lane >> 2);                           \
                b[fn][0] = __float_as_uint(sB[kc * B_STR + cn]);              \
                b[fn][1] = __float_as_uint(sB[(kc + 4) * B_STR + cn]);        \
            }                                                                 \
            _Pragma("unroll")                                                 \
            for (int fm = 0; fm < 4; fm++)                                    \
                _Pragma("unroll")                                             \
                for (int fn = 0; fn < 4; fn++)                                \
                    mma_tf32(acc[fm][fn], a[fm], b[fn]);                      \
        }                                                                     \
    }

__device__ __forceinline__ void gemm_body(
    const float* __restrict__ A, const float* __restrict__ W,
    const float* __restrict__ bias, const float* __restrict__ R,
    float* __restrict__ C, int act, size_t row0, size_t col0, char* smem)
{
    uint32_t sb = smem_u32(smem);
    int tid = threadIdx.x, lane = tid & 31, warp = tid >> 5;
    int wm = (warp & 1) * 64;
    int wn = (warp >> 1) * 32;

    if (tid < TN) *(float*)(smem + OFF_BIAS + tid * 4) = bias[col0 + tid];

    float acc[4][4][4];
    #pragma unroll
    for (int i = 0; i < 4; i++)
        #pragma unroll
        for (int j = 0; j < 4; j++)
            #pragma unroll
            for (int k = 0; k < 4; k++) acc[i][j][k] = 0.f;

    GEMM_MAINLOOP(A, W, row0, col0)

    const float* sbias = (const float*)(smem + OFF_BIAS);
    #pragma unroll
    for (int fm = 0; fm < 4; fm++) {
        size_t r0 = row0 + wm + fm * 16 + (lane >> 2);
        size_t r1 = r0 + 8;
        #pragma unroll
        for (int fn = 0; fn < 4; fn++) {
            int cl = wn + fn * 8 + 2 * (lane & 3);
            size_t cn = col0 + cl;
            float bx = sbias[cl], by = sbias[cl + 1];
            float v0 = acc[fm][fn][0] + bx;
            float v1 = acc[fm][fn][1] + by;
            float v2 = acc[fm][fn][2] + bx;
            float v3 = acc[fm][fn][3] + by;
            if (act == 1) {
                v0 = 0.5f * v0 * (1.f + erff(v0 * 0.70710678118654752f));
                v1 = 0.5f * v1 * (1.f + erff(v1 * 0.70710678118654752f));
                v2 = 0.5f * v2 * (1.f + erff(v2 * 0.70710678118654752f));
                v3 = 0.5f * v3 * (1.f + erff(v3 * 0.70710678118654752f));
            }
            if (R) {
                float2 ra = *(const float2*)(R + r0 * DD + cn);
                float2 rb = *(const float2*)(R + r1 * DD + cn);
                v0 += ra.x; v1 += ra.y; v2 += rb.x; v3 += rb.y;
            }
            *(float2*)(C + r0 * DD + cn) = make_float2(v0, v1);
            *(float2*)(C + r1 * DD + cn) = make_float2(v2, v3);
        }
    }
}

__global__ __launch_bounds__(256, 2) void pgemm_kernel(
    const float* __restrict__ A, const float* __restrict__ W,
    const float* __restrict__ bias, const float* __restrict__ R,
    float* __restrict__ C, int act)
{
    extern __shared__ char smem[];
    gemm_body(A, W, bias, R, C, act,
              (size_t)blockIdx.y * TM, (size_t)blockIdx.x * TN, smem);
}

// Fused Q/V projection: grid.x = 12 (2 matrices x 6 col-blocks)
__global__ __launch_bounds__(256, 2) void qv_gemm_kernel(
    const float* __restrict__ A,
    const float* __restrict__ Wq, const float* __restrict__ Wv,
    const float* __restrict__ bq, const float* __restrict__ bv,
    float* __restrict__ Q, float* __restrict__ V)
{
    extern __shared__ char smem[];
    int mat = blockIdx.x / (DD / TN);
    int cb  = blockIdx.x % (DD / TN);
    gemm_body(A, (mat == 0) ? Wq : Wv, (mat == 0) ? bq : bv, nullptr,
              (mat == 0) ? Q : V, 0,
              (size_t)blockIdx.y * TM, (size_t)cb * TN, smem);
}

// ---------------------------------------------------------------------------
// K-projection GEMM with fused rotary + phi epilogue. Writes PHK only;
// K never hits global memory. CTA covers 128 tokens x 2 heads.
// ---------------------------------------------------------------------------
#define KT_STR 132
#define OM_OFF (128 * KT_STR)        // floats: 16896
#define PHI_B_STR 40

__global__ __launch_bounds__(256, 2) void kphi_gemm_kernel(
    const float* __restrict__ A, const float* __restrict__ W,
    const float* __restrict__ bias, const float* __restrict__ omega,
    const float* __restrict__ cosT, const float* __restrict__ sinT,
    const int* __restrict__ mask, float* __restrict__ PHK)
{
    extern __shared__ char smem[];
    uint32_t sb = smem_u32(smem);
    int tid = threadIdx.x, lane = tid & 31, warp = tid >> 5;
    int wm = (warp & 1) * 64;
    int wn = (warp >> 1) * 32;
    size_t row0 = (size_t)blockIdx.y * TM;
    size_t col0 = (size_t)blockIdx.x * TN;

    if (tid < TN) *(float*)(smem + OFF_BIAS + tid * 4) = bias[col0 + tid];

    float acc[4][4][4];
    #pragma unroll
    for (int i = 0; i < 4; i++)
        #pragma unroll
        for (int j = 0; j < 4; j++)
            #pragma unroll
            for (int k = 0; k < 4; k++) acc[i][j][k] = 0.f;

    GEMM_MAINLOOP(A, W, row0, col0)

    // ---- fused epilogue: K tile -> smem -> rotary -> phi MMA -> PHK ----
    __syncthreads();   // all warps done reading stage buffers

    float* Kt = (float*)smem;                 // [128][132]
    float* Om = (float*)smem + OM_OFF;        // [64][40]
    const float* sbias = (const float*)(smem + OFF_BIAS);

    // store acc+bias into Kt
    #pragma unroll
    for (int fm = 0; fm < 4; fm++) {
        int r0 = wm + fm * 16 + (lane >> 2);
        #pragma unroll
        for (int fn = 0; fn < 4; fn++) {
            int cl = wn + fn * 8 + 2 * (lane & 3);
            float bx = sbias[cl], by = sbias[cl + 1];
            *(float2*)&Kt[r0 * KT_STR + cl] =
                make_float2(acc[fm][fn][0] + bx, acc[fm][fn][1] + by);
            *(float2*)&Kt[(r0 + 8) * KT_STR + cl] =
                make_float2(acc[fm][fn][2] + bx, acc[fm][fn][3] + by);
        }
    }
    // load omega (tf32 RNA)
    {
        int i0 = tid * 8;
        #pragma unroll
        for (int u = 0; u < 2; u++) {
            int i = i0 + u * 4;
            float4 v = *(const float4*)(omega + i);
            int d = i >> 5, f = i & 31;
            Om[d * PHI_B_STR + f + 0] = tf32_rna(v.x);
            Om[d * PHI_B_STR + f + 1] = tf32_rna(v.y);
            Om[d * PHI_B_STR + f + 2] = tf32_rna(v.z);
            Om[d * PHI_B_STR + f + 3] = tf32_rna(v.w);
        }
    }
    __syncthreads();

    // rotate in place: thread = one head-row (128 tokens x 2 heads)
    {
        int r  = tid >> 1;
        int hd = tid & 1;
        int n  = (int)row0 + r;
        int l  = n & (LL - 1);
        float* base = Kt + r * KT_STR + hd * 64;
        #pragma unroll
        for (int jj = 0; jj < 8; jj++) {
            int j = jj * 4;
            float4 x1 = *(float4*)(base + j);
            float4 x2 = *(float4*)(base + j + 32);
            float4 c  = *(const float4*)(cosT + l * 32 + j);
            float4 s  = *(const float4*)(sinT + l * 32 + j);
            float4 o1, o2;
            o1.x = tf32_rna(x1.x * c.x - x2.x * s.x);
            o2.x = tf32_rna(x2.x * c.x + x1.x * s.x);
            o1.y = tf32_rna(x1.y * c.y - x2.y * s.y);
            o2.y = tf32_rna(x2.y * c.y + x1.y * s.y);
            o1.z = tf32_rna(x1.z * c.z - x2.z * s.z);
            o2.z = tf32_rna(x2.z * c.z + x1.z * s.z);
            o1.w = tf32_rna(x1.w * c.w - x2.w * s.w);
            o2.w = tf32_rna(x2.w * c.w + x1.w * s.w);
            *(float4*)(base + j)      = o1;
            *(float4*)(base + j + 32) = o2;
        }
    }
    __syncthreads();

    // phi MMA: 2 passes of 128 head-rows; A(hr,k) = Kt[hr>>1][(hr&1)*64+k]
    #pragma unroll
    for (int p = 0; p < 2; p++) {
        int hrb = p * 128 + warp * 16 + (lane >> 2);
        int rk  = (hrb >> 1) * KT_STR + (hrb & 1) * 64;
        float pc[4][4];
        #pragma unroll
        for (int i = 0; i < 4; i++)
            #pragma unroll
            for (int j = 0; j < 4; j++) pc[i][j] = 0.f;
        #pragma unroll
        for (int ks = 0; ks < 8; ks++) {
            int kc = ks * 8 + (lane & 3);
            unsigned a[4];
            a[0] = __float_as_uint(Kt[rk + kc]);
            a[1] = __float_as_uint(Kt[rk + 4 * KT_STR + kc]);
            a[2] = __float_as_uint(Kt[rk + kc + 4]);
            a[3] = __float_as_uint(Kt[rk + 4 * KT_STR + kc + 4]);
            #pragma unroll
            for (int fn = 0; fn < 4; fn++) {
                int cn = fn * 8 + (lane >> 2);
                unsigned b[2];
                b[0] = __float_as_uint(Om[kc * PHI_B_STR + cn]);
                b[1] = __float_as_uint(Om[(kc + 4) * PHI_B_STR + cn]);
                mma_tf32(pc[fn], a, b);
            }
        }
        int n0 = (int)row0 + (hrb >> 1);
        int h  = 2 * blockIdx.x + (hrb & 1);
        size_t id0 = (size_t)n0 * HH + h;
        size_t id1 = (size_t)(n0 + 4) * HH + h;
        float m0 = (float)mask[n0];
        float m1 = (float)mask[n0 + 4];
        #pragma unroll
        for (int fn = 0; fn < 4; fn++) {
            int cl = fn * 8 + 2 * (lane & 3);
            *(float2*)(PHK + id0 * FDIM + cl) =
                make_float2(fmaxf(pc[fn][0], 0.f) * m0, fmaxf(pc[fn][1], 0.f) * m0);
            *(float2*)(PHK + id1 * FDIM + cl) =
                make_float2(fmaxf(pc[fn][2], 0.f) * m1, fmaxf(pc[fn][3], 0.f) * m1);
        }
    }
}

// ---------------------------------------------------------------------------
// Embedding gather
// ---------------------------------------------------------------------------
__global__ __launch_bounds__(256) void embed_kernel(
    const int* __restrict__ idx, const float* __restrict__ emb,
    float* __restrict__ X)
{
    int i   = blockIdx.x * 256 + threadIdx.x;
    int tok = i / (DD / 4);
    int c4  = i % (DD / 4);
    const float4* src = (const float4*)(emb + (size_t)idx[tok] * DD);
    ((float4*)X)[i] = src[c4];
}

// ---------------------------------------------------------------------------
// Rotary cos/sin table
// ---------------------------------------------------------------------------
__global__ __launch_bounds__(256) void rope_table_kernel(
    float* __restrict__ cosT, float* __restrict__ sinT)
{
    int i = blockIdx.x * 256 + threadIdx.x;
    int j = i & 31;
    int l = i >> 5;
    double inv = pow(10000.0, -(double)(2 * j) / (double)HDIM);
    double fr  = (double)l * inv;
    cosT[i] = (float)cos(fr);
    sinT[i] = (float)sin(fr);
}

// ---------------------------------------------------------------------------
// KV partial reduction: 4 L-chunks per (b,h), deterministic partial buffers
// ---------------------------------------------------------------------------
__global__ __launch_bounds__(256) void kv_part_kernel(
    const float* __restrict__ PHK, const float* __restrict__ V,
    float* __restrict__ KVP, float* __restrict__ KSP)
{
    __shared__ float sph[32 * FDIM];
    __shared__ float sv [32 * HDIM];
    int bh = blockIdx.x;
    int ch = blockIdx.y;
    int b  = bh / HH;
    int h  = bh % HH;
    int tid = threadIdx.x;
    int f  = tid & 31;
    int dg = tid >> 5;
    float acc[8] = {0.f,0.f,0.f,0.f,0.f,0.f,0.f,0.f};
    float sacc = 0.f;

    int rA  = tid >> 3, cA = (tid & 7) * 4;
    int lbeg = ch * (LL / KVCH), lend = lbeg + LL / KVCH;
    for (int l0 = lbeg; l0 < lend; l0 += 32) {
        *(float4*)&sph[rA * FDIM + cA] =
            *(const float4*)(PHK + ((size_t)(b * LL + l0 + rA) * HH + h) * FDIM + cA);
        #pragma unroll
        for (int p = 0; p < 2; p++) {
            int ii = tid + p * 256;
            int rr = ii >> 4, cc = (ii & 15) * 4;
            *(float4*)&sv[rr * HDIM + cc] =
                *(const float4*)(V + (size_t)(b * LL + l0 + rr) * DD + h * HDIM + cc);
        }
        __syncthreads();
        #pragma unroll 8
        for (int r = 0; r < 32; r++) {
            float ph = sph[r * FDIM + f];
            sacc += ph;
            float4 v0 = *(const float4*)&sv[r * HDIM + dg * 8];
            float4 v1 = *(const float4*)&sv[r * HDIM + dg * 8 + 4];
            acc[0] += ph * v0.x; acc[1] += ph * v0.y;
            acc[2] += ph * v0.z; acc[3] += ph * v0.w;
            acc[4] += ph * v1.x; acc[5] += ph * v1.y;
            acc[6] += ph * v1.z; acc[7] += ph * v1.w;
        }
        __syncthreads();
    }
    float* dst = KVP + (((size_t)ch * NBH + bh) * FDIM + f) * HDIM + dg * 8;
    #pragma unroll
    for (int jj = 0; jj < 8; jj++) dst[jj] = acc[jj];
    if (dg == 0) KSP[((size_t)ch * NBH + bh) * FDIM + f] = sacc;
}

__global__ __launch_bounds__(256) void kv_reduce_kernel(
    const float* __restrict__ KVP, const float* __restrict__ KSP,
    float* __restrict__ KV, float* __restrict__ KSUM)
{
    int i = blockIdx.x * 256 + threadIdx.x;
    const int NKV = NBH * FDIM * HDIM;   // 393216
    if (i < NKV) {
        float s = KVP[i] + KVP[NKV + i] + KVP[2 * NKV + i] + KVP[3 * NKV + i];
        KV[i] = s;
    }
    if (i < NBH * FDIM) {
        const int NS = NBH * FDIM;
        KSUM[i] = KSP[i] + KSP[NS + i] + KSP[2 * NS + i] + KSP[3 * NS + i];
    }
}

// ---------------------------------------------------------------------------
// Fused attention output: Y = (relu(rot(Q)@omega) @ KV) * z
// ---------------------------------------------------------------------------
#define PHI_A_STR 68
#define AT_KV_STR 72
#define AT_OFF_PS  (128 * PHI_A_STR)
#define AT_OFF_OM  (AT_OFF_PS + 128 * PHI_B_STR)
#define AT_OFF_KV  (AT_OFF_OM + HDIM * PHI_B_STR)
#define AT_OFF_DEN (AT_OFF_KV + FDIM * AT_KV_STR)
#define AT_OFF_KSM (AT_OFF_DEN + 128)
#define SMEM_ATT   ((AT_OFF_KSM + FDIM) * 4)          // 75392 bytes

__global__ __launch_bounds__(256, 2) void attn_fused_kernel(
    const float* __restrict__ Q, const float* __restrict__ omega,
    const float* __restrict__ cosT, const float* __restrict__ sinT,
    const float* __restrict__ KV, const float* __restrict__ KSUM,
    float* __restrict__ Y)
{
    extern __shared__ float sm[];
    float* As  = sm;
    float* Ps  = sm + AT_OFF_PS;
    float* Om  = sm + AT_OFF_OM;
    float* Kv  = sm + AT_OFF_KV;
    float* Den = sm + AT_OFF_DEN;
    float* Ksm = sm + AT_OFF_KSM;

    int tid = threadIdx.x, lane = tid & 31, warp = tid >> 5;
    int bh = blockIdx.y;
    int b  = bh / HH, h = bh % HH;
    int tok0 = blockIdx.x * 128;

    {
        int i0 = tid * 8;
        #pragma unroll
        for (int u = 0; u < 2; u++) {
            int i = i0 + u * 4;
            float4 v = *(const float4*)(omega + i);
            int d = i >> 5, f = i & 31;
            Om[d * PHI_B_STR + f + 0] = tf32_rna(v.x);
            Om[d * PHI_B_STR + f + 1] = tf32_rna(v.y);
            Om[d * PHI_B_STR + f + 2] = tf32_rna(v.z);
            Om[d * PHI_B_STR + f + 3] = tf32_rna(v.w);
        }
    }
    {
        const float* kvsrc = KV + (size_t)bh * FDIM * HDIM;
        int i0 = tid * 8;
        #pragma unroll
        for (int u = 0; u < 2; u++) {
            int i = i0 + u * 4;
            float4 v = *(const float4*)(kvsrc + i);
            int f = i >> 6, d = i & 63;
            *(float4*)&Kv[f * AT_KV_STR + d] = v;
        }
    }
    if (tid < FDIM) Ksm[tid] = KSUM[bh * FDIM + tid];

    {
        int row = tid >> 1;
        int j0  = (tid & 1) * 16;
        int l   = tok0 + row;
        const float* xp = Q + ((size_t)(b * LL) + l) * DD + h * HDIM;
        #pragma unroll
        for (int jj = 0; jj < 4; jj++) {
            int j = j0 + jj * 4;
            float4 x1 = *(const float4*)(xp + j);
            float4 x2 = *(const float4*)(xp + j + 32);
            float4 c  = *(const float4*)(cosT + l * 32 + j);
            float4 s  = *(const float4*)(sinT + l * 32 + j);
            float* a1 = As + row * PHI_A_STR + j;
            a1[0]  = tf32_rna(x1.x * c.x - x2.x * s.x);
            a1[32] = tf32_rna(x2.x * c.x + x1.x * s.x);
            a1[1]  = tf32_rna(x1.y * c.y - x2.y * s.y);
            a1[33] = tf32_rna(x2.y * c.y + x1.y * s.y);
            a1[2]  = tf32_rna(x1.z * c.z - x2.z * s.z);
            a1[34] = tf32_rna(x2.z * c.z + x1.z * s.z);
            a1[3]  = tf32_rna(x1.w * c.w - x2.w * s.w);
            a1[35] = tf32_rna(x2.w * c.w + x1.w * s.w);
        }
    }
    __syncthreads();

    int rbase = warp * 16 + (lane >> 2);

    {
        float p[4][4];
        #pragma unroll
        for (int i = 0; i < 4; i++)
            #pragma unroll
            for (int j = 0; j < 4; j++) p[i][j] = 0.f;
        #pragma unroll
        for (int ks = 0; ks < 8; ks++) {
            int kc = ks * 8 + (lane & 3);
            unsigned a[4];
            a[0] = __float_as_uint(As[rbase * PHI_A_STR + kc]);
            a[1] = __float_as_uint(As[(rbase + 8) * PHI_A_STR + kc]);
            a[2] = __float_as_uint(As[rbase * PHI_A_STR + kc + 4]);
            a[3] = __float_as_uint(As[(rbase + 8) * PHI_A_STR + kc + 4]);
            #pragma unroll
            for (int fn = 0; fn < 4; fn++) {
                int cn = fn * 8 + (lane >> 2);
                unsigned bb[2];
                bb[0] = __float_as_uint(Om[kc * PHI_B_STR + cn]);
                bb[1] = __float_as_uint(Om[(kc + 4) * PHI_B_STR + cn]);
                mma_tf32(p[fn], a, bb);
            }
        }
        #pragma unroll
        for (int fn = 0; fn < 4; fn++) {
            int cl = fn * 8 + 2 * (lane & 3);
            Ps[rbase * PHI_B_STR + cl]           = fmaxf(p[fn][0], 0.f);
            Ps[rbase * PHI_B_STR + cl + 1]       = fmaxf(p[fn][1], 0.f);
            Ps[(rbase + 8) * PHI_B_STR + cl]     = fmaxf(p[fn][2], 0.f);
            Ps[(rbase + 8) * PHI_B_STR + cl + 1] = fmaxf(p[fn][3], 0.f);
        }
    }
    __syncthreads();

    if (tid < 128) {
        float s = ATTN_EPS;
        #pragma unroll
        for (int f = 0; f < FDIM; f++) s += Ps[tid * PHI_B_STR + f] * Ksm[f];
        Den[tid] = 1.0f / s;
    }
    __syncthreads();

    float o[8][4];
    #pragma unroll
    for (int i = 0; i < 8; i++)
        #pragma unroll
        for (int j = 0; j < 4; j++) o[i][j] = 0.f;
    #pragma unroll
    for (int ks = 0; ks < 4; ks++) {
        int kc = ks * 8 + (lane & 3);
        unsigned a[4];
        a[0] = __float_as_uint(Ps[rbase * PHI_B_STR + kc]);
        a[1] = __float_as_uint(Ps[(rbase + 8) * PHI_B_STR + kc]);
        a[2] = __float_as_uint(Ps[rbase * PHI_B_STR + kc + 4]);
        a[3] = __float_as_uint(Ps[(rbase + 8) * PHI_B_STR + kc + 4]);
        #pragma unroll
        for (int fn = 0; fn < 8; fn++) {
            int cn = fn * 8 + (lane >> 2);
            unsigned bb[2];
            bb[0] = __float_as_uint(Kv[kc * AT_KV_STR + cn]);
            bb[1] = __float_as_uint(Kv[(kc + 4) * AT_KV_STR + cn]);
            mma_tf32(o[fn], a, bb);
        }
    }

    float z0 = Den[rbase];
    float z1 = Den[rbase + 8];
    size_t t0 = (size_t)(b * LL + tok0) + rbase;
    float* y0 = Y + t0 * DD + h * HDIM;
    float* y1 = Y + (t0 + 8) * DD + h * HDIM;
    #pragma unroll
    for (int fn = 0; fn < 8; fn++) {
        int cl = fn * 8 + 2 * (lane & 3);
        *(float2*)(y0 + cl) = make_float2(o[fn][0] * z0, o[fn][1] * z0);
        *(float2*)(y1 + cl) = make_float2(o[fn][2] * z1, o[fn][3] * z1);
    }
}

// ---------------------------------------------------------------------------
// Warp-per-row LayerNorm
// ---------------------------------------------------------------------------
__global__ __launch_bounds__(256) void ln_kernel(
    const float* __restrict__ in, const float* __restrict__ g,
    const float* __restrict__ b, float* __restrict__ out)
{
    int warp = threadIdx.x >> 5, lane = threadIdx.x & 31;
    size_t row = (size_t)blockIdx.x * 8 + warp;
    const float4* ip = (const float4*)(in + row * DD);

    float4 x[6];
    float s = 0.f, s2 = 0.f;
    #pragma unroll
    for (int i = 0; i < 6; i++) {
        x[i] = ip[lane + i * 32];
        s  += x[i].x + x[i].y + x[i].z + x[i].w;
        s2 += x[i].x * x[i].x + x[i].y * x[i].y
            + x[i].z * x[i].z + x[i].w * x[i].w;
    }
    #pragma unroll
    for (int off = 16; off > 0; off >>= 1) {
        s  += __shfl_xor_sync(0xFFFFFFFF, s,  off);
        s2 += __shfl_xor_sync(0xFFFFFFFF, s2, off);
    }
    float mu   = s * (1.0f / DD);
    float rstd = rsqrtf(s2 * (1.0f / DD) - mu * mu + LN_EPS);

    const float4* gp = (const float4*)g;
    const float4* bp = (const float4*)b;
    float4* op = (float4*)(out + row * DD);
    #pragma unroll
    for (int i = 0; i < 6; i++) {
        float4 gg = gp[lane + i * 32];
        float4 bb = bp[lane + i * 32];
        float4 o;
        o.x = (x[i].x - mu) * rstd * gg.x + bb.x;
        o.y = (x[i].y - mu) * rstd * gg.y + bb.y;
        o.z = (x[i].z - mu) * rstd * gg.z + bb.z;
        o.w = (x[i].w - mu) * rstd * gg.w + bb.w;
        op[lane + i * 32] = o;
    }
}

// ---------------------------------------------------------------------------
// Host orchestration
// ---------------------------------------------------------------------------
extern "C" void kernel_launch(void* const* d_in, const int* in_sizes, int n_in,
                              void* d_out, int out_size)
{
    const int*   idx     = (const int*)  d_in[0];
    const int*   mask    = (const int*)  d_in[1];
    const float* tok_emb = (const float*)d_in[2];
    const float* Wq = (const float*)d_in[3];
    const float* bq = (const float*)d_in[4];
    const float* Wk = (const float*)d_in[5];
    const float* bk = (const float*)d_in[6];
    const float* Wv = (const float*)d_in[7];
    const float* bv = (const float*)d_in[8];
    const float* Wo = (const float*)d_in[9];
    const float* bo = (const float*)d_in[10];
    const float* om = (const float*)d_in[11];
    const float* W1 = (const float*)d_in[12];
    const float* b1 = (const float*)d_in[13];
    const float* W2 = (const float*)d_in[14];
    const float* b2 = (const float*)d_in[15];
    const float* g1 = (const float*)d_in[16];
    const float* be1= (const float*)d_in[17];
    const float* g2 = (const float*)d_in[18];
    const float* be2= (const float*)d_in[19];
    const float* gf = (const float*)d_in[20];
    const float* bf = (const float*)d_in[21];
    float* out = (float*)d_out;

    float *X, *Y, *Q, *V, *PHK, *KV, *KSUM, *KVP, *KSP, *COS, *SIN;
    cudaGetSymbolAddress((void**)&X,    g_X);
    cudaGetSymbolAddress((void**)&Y,    g_Y);
    cudaGetSymbolAddress((void**)&Q,    g_Q);
    cudaGetSymbolAddress((void**)&V,    g_V);
    cudaGetSymbolAddress((void**)&PHK,  g_PHK);
    cudaGetSymbolAddress((void**)&KV,   g_KV);
    cudaGetSymbolAddress((void**)&KSUM, g_KSUM);
    cudaGetSymbolAddress((void**)&KVP,  g_KVP);
    cudaGetSymbolAddress((void**)&KSP,  g_KSP);
    cudaGetSymbolAddress((void**)&COS,  g_COS);
    cudaGetSymbolAddress((void**)&SIN,  g_SIN);

    cudaFuncSetAttribute(pgemm_kernel,
                         cudaFuncAttributeMaxDynamicSharedMemorySize, SMEM_GEMM);
    cudaFuncSetAttribute(qv_gemm_kernel,
                         cudaFuncAttributeMaxDynamicSharedMemorySize, SMEM_GEMM);
    cudaFuncSetAttribute(kphi_gemm_kernel,
                         cudaFuncAttributeMaxDynamicSharedMemorySize, SMEM_GEMM);
    cudaFuncSetAttribute(attn_fused_kernel,
                         cudaFuncAttributeMaxDynamicSharedMemorySize, SMEM_ATT);

    const size_t WMAT = (size_t)DD * DD;
    dim3 gGrid(DD / TN, NTOK / TM);       // (6, 256)
    dim3 qvGrid(2 * DD / TN, NTOK / TM);  // (12, 256)
    dim3 attGrid(LL / 128, NBH);          // (16, 192)

    rope_table_kernel<<<(LL * 32) / 256, 256>>>(COS, SIN);
    embed_kernel<<<(NTOK * DD / 4) / 256, 256>>>(idx, tok_emb, X);

    for (int i = 0; i < NLAYER; i++) {
        const float* om_i = om + (size_t)i * HDIM * FDIM;

        kphi_gemm_kernel<<<gGrid, 256, SMEM_GEMM>>>(
            X, Wk + i * WMAT, bk + i * DD, om_i, COS, SIN, mask, PHK);
        qv_gemm_kernel<<<qvGrid, 256, SMEM_GEMM>>>(
            X, Wq + i * WMAT, Wv + i * WMAT, bq + i * DD, bv + i * DD, Q, V);

        kv_part_kernel<<<dim3(NBH, KVCH), 256>>>(PHK, V, KVP, KSP);
        kv_reduce_kernel<<<(NBH * FDIM * HDIM) / 256, 256>>>(KVP, KSP, KV, KSUM);

        attn_fused_kernel<<<attGrid, 256, SMEM_ATT>>>(
            Q, om_i, COS, SIN, KV, KSUM, Y);

        // X = Y @ Wo + bo + X
        pgemm_kernel<<<gGrid, 256, SMEM_GEMM>>>(Y, Wo + i * WMAT, bo + i * DD, X, X, 0);
        ln_kernel<<<NTOK / 8, 256>>>(X, g1 + i * DD, be1 + i * DD, X);
        // Q = gelu(X @ W1 + b1)
        pgemm_kernel<<<gGrid, 256, SMEM_GEMM>>>(X, W1 + i * WMAT, b1 + i * DD, nullptr, Q, 1);
        // Y = Q @ W2 + b2 + X
        pgemm_kernel<<<gGrid, 256, SMEM_GEMM>>>(Q, W2 + i * WMAT, b2 + i * DD, X, Y, 0);
        ln_kernel<<<NTOK / 8, 256>>>(Y, g2 + i * DD, be2 + i * DD, X);
    }

    ln_kernel<<<NTOK / 8, 256>>>(X, gf, bf, out);
}

// round 14
// speedup vs baseline: 1.0122x; 1.0122x over previous
#include <cuda_runtime.h>
#include <math.h>
#include <stdint.h>

// Problem constants
#define BB      16
#define LL      2048
#define DD      768
#define HH      12
#define NLAYER  4
#define FDIM    32
#define HDIM    64
#define NTOK    (BB * LL)            // 32768
#define ATTN_EPS 1e-6f
#define LN_EPS   1e-5f
#define NBH     (BB * HH)            // 192
#define KVCH    4                    // kv L-split chunks
#define NKV     (NBH * FDIM * HDIM)  // 393216
#define NKS     (NBH * FDIM)

// ---------------------------------------------------------------------------
// Scratch buffers
// ---------------------------------------------------------------------------
__device__ float g_X [(size_t)NTOK * DD];
__device__ float g_Y [(size_t)NTOK * DD];
__device__ float g_Q [(size_t)NTOK * DD];
__device__ float g_K [(size_t)NTOK * DD];
__device__ float g_V [(size_t)NTOK * DD];
__device__ float g_PHK[(size_t)NTOK * HH * FDIM];
__device__ float g_KVP [KVCH * NKV];
__device__ float g_KSP [KVCH * NKS];
__device__ float g_COS [LL * (HDIM / 2)];
__device__ float g_SIN [LL * (HDIM / 2)];

// ---------------------------------------------------------------------------
// PTX helpers
// ---------------------------------------------------------------------------
__device__ __forceinline__ void cpa16(uint32_t d, const void* s) {
    asm volatile("cp.async.cg.shared.global [%0], [%1], 16;" :: "r"(d), "l"(s));
}
#define CPA_COMMIT() asm volatile("cp.async.commit_group;" ::: "memory")
#define CPA_WAIT1()  asm volatile("cp.async.wait_group 1;" ::: "memory")

__device__ __forceinline__ uint32_t smem_u32(const void* p) {
    uint32_t a;
    asm("{ .reg .u64 t; cvta.to.shared.u64 t, %1; cvt.u32.u64 %0, t; }"
        : "=r"(a) : "l"(p));
    return a;
}

__device__ __forceinline__ float tf32_rna(float x) {
    unsigned r;
    asm("cvt.rna.tf32.f32 %0, %1;" : "=r"(r) : "f"(x));
    return __uint_as_float(r);
}

__device__ __forceinline__ void mma_tf32(float* c, const unsigned* a, const unsigned* b) {
    asm volatile(
        "mma.sync.aligned.m16n8k8.row.col.f32.tf32.tf32.f32 "
        "{%0,%1,%2,%3},{%4,%5,%6,%7},{%8,%9},{%0,%1,%2,%3};"
        : "+f"(c[0]), "+f"(c[1]), "+f"(c[2]), "+f"(c[3])
        : "r"(a[0]), "r"(a[1]), "r"(a[2]), "r"(a[3]), "r"(b[0]), "r"(b[1]));
}

// ---------------------------------------------------------------------------
// GEMM body (R4-proven shape): 128x128x32 tile, 8 warps of 64x32,
// cp.async 3-stage. Shared by pgemm_kernel and qkv_gemm_kernel.
// ---------------------------------------------------------------------------
#define TM 128
#define TN 128
#define TBK 32
#define NST 3
#define A_STR 36
#define B_STR 136
#define A_TILE_B (TM * A_STR * 4)           // 18432
#define B_TILE_B (TBK * B_STR * 4)          // 17408
#define STAGE_B  (A_TILE_B + B_TILE_B)      // 35840
#define OFF_BIAS (NST * STAGE_B)            // 107520
#define SMEM_GEMM (OFF_BIAS + TN * 4)       // 108032
#define NKT (DD / TBK)                      // 24

__device__ __forceinline__ void gemm_body(
    const float* __restrict__ A, const float* __restrict__ W,
    const float* __restrict__ bias, const float* __restrict__ R,
    float* __restrict__ C, int act, size_t row0, size_t col0, char* smem)
{
    uint32_t sb = smem_u32(smem);
    int tid = threadIdx.x, lane = tid & 31, warp = tid >> 5;
    int wm = (warp & 1) * 64;
    int wn = (warp >> 1) * 32;

    if (tid < TN) *(float*)(smem + OFF_BIAS + tid * 4) = bias[col0 + tid];

    int ar = tid >> 3, akc = tid & 7;
    int bk = tid >> 5, bnc = tid & 31;
    auto load_stage = [&](int u) {
        uint32_t st = sb + (u % NST) * STAGE_B;
        int k0 = u * TBK;
        #pragma unroll
        for (int i = 0; i < 4; i++) {
            int r = ar + i * 32;
            cpa16(st + r * (A_STR * 4) + akc * 16,
                  A + (row0 + r) * DD + k0 + akc * 4);
        }
        uint32_t bbase = st + A_TILE_B;
        #pragma unroll
        for (int i = 0; i < 4; i++) {
            int k = bk + i * 8;
            cpa16(bbase + k * (B_STR * 4) + bnc * 16,
                  W + (size_t)(k0 + k) * DD + col0 + bnc * 4);
        }
    };

    float acc[4][4][4];
    #pragma unroll
    for (int i = 0; i < 4; i++)
        #pragma unroll
        for (int j = 0; j < 4; j++)
            #pragma unroll
            for (int k = 0; k < 4; k++) acc[i][j][k] = 0.f;

    load_stage(0); CPA_COMMIT();
    load_stage(1); CPA_COMMIT();

    for (int t = 0; t < NKT; t++) {
        CPA_WAIT1();
        __syncthreads();
        if (t + 2 < NKT) load_stage(t + 2);
        CPA_COMMIT();
        const float* sA = (const float*)(smem + (t % NST) * STAGE_B);
        const float* sB = (const float*)(smem + (t % NST) * STAGE_B + A_TILE_B);
        #pragma unroll
        for (int ks = 0; ks < 4; ks++) {
            int kc = ks * 8 + (lane & 3);
            unsigned a[4][4], b[4][2];
            #pragma unroll
            for (int fm = 0; fm < 4; fm++) {
                int r = wm + fm * 16 + (lane >> 2);
                a[fm][0] = __float_as_uint(sA[r * A_STR + kc]);
                a[fm][1] = __float_as_uint(sA[(r + 8) * A_STR + kc]);
                a[fm][2] = __float_as_uint(sA[r * A_STR + kc + 4]);
                a[fm][3] = __float_as_uint(sA[(r + 8) * A_STR + kc + 4]);
            }
            #pragma unroll
            for (int fn = 0; fn < 4; fn++) {
                int cn = wn + fn * 8 + (lane >> 2);
                b[fn][0] = __float_as_uint(sB[kc * B_STR + cn]);
                b[fn][1] = __float_as_uint(sB[(kc + 4) * B_STR + cn]);
            }
            #pragma unroll
            for (int fm = 0; fm < 4; fm++)
                #pragma unroll
                for (int fn = 0; fn < 4; fn++)
                    mma_tf32(acc[fm][fn], a[fm], b[fn]);
        }
    }

    const float* sbias = (const float*)(smem + OFF_BIAS);
    #pragma unroll
    for (int fm = 0; fm < 4; fm++) {
        size_t r0 = row0 + wm + fm * 16 + (lane >> 2);
        size_t r1 = r0 + 8;
        #pragma unroll
        for (int fn = 0; fn < 4; fn++) {
            int cl = wn + fn * 8 + 2 * (lane & 3);
            size_t cn = col0 + cl;
            float bx = sbias[cl], by = sbias[cl + 1];
            float v0 = acc[fm][fn][0] + bx;
            float v1 = acc[fm][fn][1] + by;
            float v2 = acc[fm][fn][2] + bx;
            float v3 = acc[fm][fn][3] + by;
            if (act == 1) {
                v0 = 0.5f * v0 * (1.f + erff(v0 * 0.70710678118654752f));
                v1 = 0.5f * v1 * (1.f + erff(v1 * 0.70710678118654752f));
                v2 = 0.5f * v2 * (1.f + erff(v2 * 0.70710678118654752f));
                v3 = 0.5f * v3 * (1.f + erff(v3 * 0.70710678118654752f));
            }
            if (R) {
                float2 ra = *(const float2*)(R + r0 * DD + cn);
                float2 rb = *(const float2*)(R + r1 * DD + cn);
                v0 += ra.x; v1 += ra.y; v2 += rb.x; v3 += rb.y;
            }
            *(float2*)(C + r0 * DD + cn) = make_float2(v0, v1);
            *(float2*)(C + r1 * DD + cn) = make_float2(v2, v3);
        }
    }
}

__global__ __launch_bounds__(256, 2) void pgemm_kernel(
    const float* __restrict__ A, const float* __restrict__ W,
    const float* __restrict__ bias, const float* __restrict__ R,
    float* __restrict__ C, int act)
{
    extern __shared__ char smem[];
    gemm_body(A, W, bias, R, C, act,
              (size_t)blockIdx.y * TM, (size_t)blockIdx.x * TN, smem);
}

// Fused Q/K/V projection: grid.x = 18 (3 matrices x 6 col-blocks)
__global__ __launch_bounds__(256, 2) void qkv_gemm_kernel(
    const float* __restrict__ A,
    const float* __restrict__ Wq, const float* __restrict__ Wk,
    const float* __restrict__ Wv,
    const float* __restrict__ bq, const float* __restrict__ bk,
    const float* __restrict__ bv,
    float* __restrict__ Q, float* __restrict__ K, float* __restrict__ V)
{
    extern __shared__ char smem[];
    int mat = blockIdx.x / (DD / TN);
    int cb  = blockIdx.x % (DD / TN);
    const float* W  = (mat == 0) ? Wq : (mat == 1) ? Wk : Wv;
    const float* bi = (mat == 0) ? bq : (mat == 1) ? bk : bv;
    float*       C  = (mat == 0) ? Q  : (mat == 1) ? K  : V;
    gemm_body(A, W, bi, nullptr, C, 0,
              (size_t)blockIdx.y * TM, (size_t)cb * TN, smem);
}

// ---------------------------------------------------------------------------
// Embedding gather
// ---------------------------------------------------------------------------
__global__ __launch_bounds__(256) void embed_kernel(
    const int* __restrict__ idx, const float* __restrict__ emb,
    float* __restrict__ X)
{
    int i   = blockIdx.x * 256 + threadIdx.x;
    int tok = i / (DD / 4);
    int c4  = i % (DD / 4);
    const float4* src = (const float4*)(emb + (size_t)idx[tok] * DD);
    ((float4*)X)[i] = src[c4];
}

// ---------------------------------------------------------------------------
// Rotary cos/sin table
// ---------------------------------------------------------------------------
__global__ __launch_bounds__(256) void rope_table_kernel(
    float* __restrict__ cosT, float* __restrict__ sinT)
{
    int i = blockIdx.x * 256 + threadIdx.x;
    int j = i & 31;
    int l = i >> 5;
    double inv = pow(10000.0, -(double)(2 * j) / (double)HDIM);
    double fr  = (double)l * inv;
    cosT[i] = (float)cos(fr);
    sinT[i] = (float)sin(fr);
}

// ---------------------------------------------------------------------------
// Tensor-core phi for K only: PHK = relu( rot(K) @ omega ) * mask
// ---------------------------------------------------------------------------
#define PHI_A_STR 68
#define PHI_B_STR 40
#define SMEM_PHI ((128 * PHI_A_STR + HDIM * PHI_B_STR) * 4)   // 45056 bytes

__global__ __launch_bounds__(256, 2) void phik_mma_kernel(
    const float* __restrict__ K, const float* __restrict__ omega,
    const float* __restrict__ cosT, const float* __restrict__ sinT,
    const int* __restrict__ mask, float* __restrict__ PHK)
{
    extern __shared__ float sm[];
    float* As = sm;
    float* Bs = sm + 128 * PHI_A_STR;

    int tid = threadIdx.x, lane = tid & 31, warp = tid >> 5;

    {
        int i0 = tid * 8;
        #pragma unroll
        for (int u = 0; u < 2; u++) {
            int i = i0 + u * 4;
            float4 v = *(const float4*)(omega + i);
            int d = i >> 5, f = i & 31;
            Bs[d * PHI_B_STR + f + 0] = tf32_rna(v.x);
            Bs[d * PHI_B_STR + f + 1] = tf32_rna(v.y);
            Bs[d * PHI_B_STR + f + 2] = tf32_rna(v.z);
            Bs[d * PHI_B_STR + f + 3] = tf32_rna(v.w);
        }
    }

    {
        int row = tid >> 1;
        int j0  = (tid & 1) * 16;
        int id  = blockIdx.x * 128 + row;
        int n   = id / HH;
        int l   = n & (LL - 1);
        const float* xp = K + (size_t)n * DD + (id % HH) * HDIM;
        #pragma unroll
        for (int jj = 0; jj < 4; jj++) {
            int j = j0 + jj * 4;
            float4 x1 = *(const float4*)(xp + j);
            float4 x2 = *(const float4*)(xp + j + 32);
            float4 c  = *(const float4*)(cosT + l * 32 + j);
            float4 s  = *(const float4*)(sinT + l * 32 + j);
            float* a1 = As + row * PHI_A_STR + j;
            a1[0]  = tf32_rna(x1.x * c.x - x2.x * s.x);
            a1[32] = tf32_rna(x2.x * c.x + x1.x * s.x);
            a1[1]  = tf32_rna(x1.y * c.y - x2.y * s.y);
            a1[33] = tf32_rna(x2.y * c.y + x1.y * s.y);
            a1[2]  = tf32_rna(x1.z * c.z - x2.z * s.z);
            a1[34] = tf32_rna(x2.z * c.z + x1.z * s.z);
            a1[3]  = tf32_rna(x1.w * c.w - x2.w * s.w);
            a1[35] = tf32_rna(x2.w * c.w + x1.w * s.w);
        }
    }
    __syncthreads();

    float acc[4][4];
    #pragma unroll
    for (int i = 0; i < 4; i++)
        #pragma unroll
        for (int j = 0; j < 4; j++) acc[i][j] = 0.f;

    int rbase = warp * 16 + (lane >> 2);
    #pragma unroll
    for (int ks = 0; ks < 8; ks++) {
        int kc = ks * 8 + (lane & 3);
        unsigned a[4];
        a[0] = __float_as_uint(As[rbase * PHI_A_STR + kc]);
        a[1] = __float_as_uint(As[(rbase + 8) * PHI_A_STR + kc]);
        a[2] = __float_as_uint(As[rbase * PHI_A_STR + kc + 4]);
        a[3] = __float_as_uint(As[(rbase + 8) * PHI_A_STR + kc + 4]);
        #pragma unroll
        for (int fn = 0; fn < 4; fn++) {
            int cn = fn * 8 + (lane >> 2);
            unsigned b[2];
            b[0] = __float_as_uint(Bs[kc * PHI_B_STR + cn]);
            b[1] = __float_as_uint(Bs[(kc + 4) * PHI_B_STR + cn]);
            mma_tf32(acc[fn], a, b);
        }
    }

    size_t id0 = (size_t)blockIdx.x * 128 + warp * 16 + (lane >> 2);
    size_t id1 = id0 + 8;
    float m0 = (float)mask[id0 / HH];
    float m1 = (float)mask[id1 / HH];
    #pragma unroll
    for (int fn = 0; fn < 4; fn++) {
        int cl = fn * 8 + 2 * (lane & 3);
        *(float2*)(PHK + id0 * FDIM + cl) =
            make_float2(fmaxf(acc[fn][0], 0.f) * m0, fmaxf(acc[fn][1], 0.f) * m0);
        *(float2*)(PHK + id1 * FDIM + cl) =
            make_float2(fmaxf(acc[fn][2], 0.f) * m1, fmaxf(acc[fn][3], 0.f) * m1);
    }
}

// ---------------------------------------------------------------------------
// KV partial reduction: 4 L-chunks per (b,h), deterministic partial buffers
// ---------------------------------------------------------------------------
__global__ __launch_bounds__(256) void kv_part_kernel(
    const float* __restrict__ PHK, const float* __restrict__ V,
    float* __restrict__ KVP, float* __restrict__ KSP)
{
    __shared__ float sph[32 * FDIM];
    __shared__ float sv [32 * HDIM];
    int bh = blockIdx.x;
    int ch = blockIdx.y;
    int b  = bh / HH;
    int h  = bh % HH;
    int tid = threadIdx.x;
    int f  = tid & 31;
    int dg = tid >> 5;
    float acc[8] = {0.f,0.f,0.f,0.f,0.f,0.f,0.f,0.f};
    float sacc = 0.f;

    int rA  = tid >> 3, cA = (tid & 7) * 4;
    int lbeg = ch * (LL / KVCH), lend = lbeg + LL / KVCH;
    for (int l0 = lbeg; l0 < lend; l0 += 32) {
        *(float4*)&sph[rA * FDIM + cA] =
            *(const float4*)(PHK + ((size_t)(b * LL + l0 + rA) * HH + h) * FDIM + cA);
        #pragma unroll
        for (int p = 0; p < 2; p++) {
            int ii = tid + p * 256;
            int rr = ii >> 4, cc = (ii & 15) * 4;
            *(float4*)&sv[rr * HDIM + cc] =
                *(const float4*)(V + (size_t)(b * LL + l0 + rr) * DD + h * HDIM + cc);
        }
        __syncthreads();
        #pragma unroll 8
        for (int r = 0; r < 32; r++) {
            float ph = sph[r * FDIM + f];
            sacc += ph;
            float4 v0 = *(const float4*)&sv[r * HDIM + dg * 8];
            float4 v1 = *(const float4*)&sv[r * HDIM + dg * 8 + 4];
            acc[0] += ph * v0.x; acc[1] += ph * v0.y;
            acc[2] += ph * v0.z; acc[3] += ph * v0.w;
            acc[4] += ph * v1.x; acc[5] += ph * v1.y;
            acc[6] += ph * v1.z; acc[7] += ph * v1.w;
        }
        __syncthreads();
    }
    float* dst = KVP + (((size_t)ch * NBH + bh) * FDIM + f) * HDIM + dg * 8;
    #pragma unroll
    for (int jj = 0; jj < 8; jj++) dst[jj] = acc[jj];
    if (dg == 0) KSP[((size_t)ch * NBH + bh) * FDIM + f] = sacc;
}

// ---------------------------------------------------------------------------
// Fused attention output: Y = (relu(rot(Q)@omega) @ KV) * z
// KV/KSUM are reduced from the 4 partial buffers during the load phase
// (same summation order as the old kv_reduce kernel -> bitwise identical).
// ---------------------------------------------------------------------------
#define AT_KV_STR 72
#define AT_OFF_PS  (128 * PHI_A_STR)
#define AT_OFF_OM  (AT_OFF_PS + 128 * PHI_B_STR)
#define AT_OFF_KV  (AT_OFF_OM + HDIM * PHI_B_STR)
#define AT_OFF_DEN (AT_OFF_KV + FDIM * AT_KV_STR)
#define AT_OFF_KSM (AT_OFF_DEN + 128)
#define SMEM_ATT   ((AT_OFF_KSM + FDIM) * 4)          // 75392 bytes

__global__ __launch_bounds__(256, 2) void attn_fused_kernel(
    const float* __restrict__ Q, const float* __restrict__ omega,
    const float* __restrict__ cosT, const float* __restrict__ sinT,
    const float* __restrict__ KVP, const float* __restrict__ KSP,
    float* __restrict__ Y)
{
    extern __shared__ float sm[];
    float* As  = sm;
    float* Ps  = sm + AT_OFF_PS;
    float* Om  = sm + AT_OFF_OM;
    float* Kv  = sm + AT_OFF_KV;
    float* Den = sm + AT_OFF_DEN;
    float* Ksm = sm + AT_OFF_KSM;

    int tid = threadIdx.x, lane = tid & 31, warp = tid >> 5;
    int bh = blockIdx.y;
    int b  = bh / HH, h = bh % HH;
    int tok0 = blockIdx.x * 128;

    {
        int i0 = tid * 8;
        #pragma unroll
        for (int u = 0; u < 2; u++) {
            int i = i0 + u * 4;
            float4 v = *(const float4*)(omega + i);
            int d = i >> 5, f = i & 31;
            Om[d * PHI_B_STR + f + 0] = tf32_rna(v.x);
            Om[d * PHI_B_STR + f + 1] = tf32_rna(v.y);
            Om[d * PHI_B_STR + f + 2] = tf32_rna(v.z);
            Om[d * PHI_B_STR + f + 3] = tf32_rna(v.w);
        }
    }
    // KV tile: reduce the 4 partials while staging into smem [f][72]
    {
        const float* kv0 = KVP + (size_t)bh * FDIM * HDIM;
        int i0 = tid * 8;
        #pragma unroll
        for (int u = 0; u < 2; u++) {
            int i = i0 + u * 4;
            float4 v0 = *(const float4*)(kv0 + i);
            float4 v1 = *(const float4*)(kv0 + NKV + i);
            float4 v2 = *(const float4*)(kv0 + 2 * (size_t)NKV + i);
            float4 v3 = *(const float4*)(kv0 + 3 * (size_t)NKV + i);
            float4 v;
            v.x = v0.x + v1.x + v2.x + v3.x;
            v.y = v0.y + v1.y + v2.y + v3.y;
            v.z = v0.z + v1.z + v2.z + v3.z;
            v.w = v0.w + v1.w + v2.w + v3.w;
            int f = i >> 6, d = i & 63;
            *(float4*)&Kv[f * AT_KV_STR + d] = v;
        }
    }
    if (tid < FDIM) {
        int i = bh * FDIM + tid;
        Ksm[tid] = KSP[i] + KSP[NKS + i] + KSP[2 * NKS + i] + KSP[3 * NKS + i];
    }

    {
        int row = tid >> 1;
        int j0  = (tid & 1) * 16;
        int l   = tok0 + row;
        const float* xp = Q + ((size_t)(b * LL) + l) * DD + h * HDIM;
        #pragma unroll
        for (int jj = 0; jj < 4; jj++) {
            int j = j0 + jj * 4;
            float4 x1 = *(const float4*)(xp + j);
            float4 x2 = *(const float4*)(xp + j + 32);
            float4 c  = *(const float4*)(cosT + l * 32 + j);
            float4 s  = *(const float4*)(sinT + l * 32 + j);
            float* a1 = As + row * PHI_A_STR + j;
            a1[0]  = tf32_rna(x1.x * c.x - x2.x * s.x);
            a1[32] = tf32_rna(x2.x * c.x + x1.x * s.x);
            a1[1]  = tf32_rna(x1.y * c.y - x2.y * s.y);
            a1[33] = tf32_rna(x2.y * c.y + x1.y * s.y);
            a1[2]  = tf32_rna(x1.z * c.z - x2.z * s.z);
            a1[34] = tf32_rna(x2.z * c.z + x1.z * s.z);
            a1[3]  = tf32_rna(x1.w * c.w - x2.w * s.w);
            a1[35] = tf32_rna(x2.w * c.w + x1.w * s.w);
        }
    }
    __syncthreads();

    int rbase = warp * 16 + (lane >> 2);

    {
        float p[4][4];
        #pragma unroll
        for (int i = 0; i < 4; i++)
            #pragma unroll
            for (int j = 0; j < 4; j++) p[i][j] = 0.f;
        #pragma unroll
        for (int ks = 0; ks < 8; ks++) {
            int kc = ks * 8 + (lane & 3);
            unsigned a[4];
            a[0] = __float_as_uint(As[rbase * PHI_A_STR + kc]);
            a[1] = __float_as_uint(As[(rbase + 8) * PHI_A_STR + kc]);
            a[2] = __float_as_uint(As[rbase * PHI_A_STR + kc + 4]);
            a[3] = __float_as_uint(As[(rbase + 8) * PHI_A_STR + kc + 4]);
            #pragma unroll
            for (int fn = 0; fn < 4; fn++) {
                int cn = fn * 8 + (lane >> 2);
                unsigned bb[2];
                bb[0] = __float_as_uint(Om[kc * PHI_B_STR + cn]);
                bb[1] = __float_as_uint(Om[(kc + 4) * PHI_B_STR + cn]);
                mma_tf32(p[fn], a, bb);
            }
        }
        #pragma unroll
        for (int fn = 0; fn < 4; fn++) {
            int cl = fn * 8 + 2 * (lane & 3);
            Ps[rbase * PHI_B_STR + cl]           = fmaxf(p[fn][0], 0.f);
            Ps[rbase * PHI_B_STR + cl + 1]       = fmaxf(p[fn][1], 0.f);
            Ps[(rbase + 8) * PHI_B_STR + cl]     = fmaxf(p[fn][2], 0.f);
            Ps[(rbase + 8) * PHI_B_STR + cl + 1] = fmaxf(p[fn][3], 0.f);
        }
    }
    __syncthreads();

    if (tid < 128) {
        float s = ATTN_EPS;
        #pragma unroll
        for (int f = 0; f < FDIM; f++) s += Ps[tid * PHI_B_STR + f] * Ksm[f];
        Den[tid] = 1.0f / s;
    }
    __syncthreads();

    float o[8][4];
    #pragma unroll
    for (int i = 0; i < 8; i++)
        #pragma unroll
        for (int j = 0; j < 4; j++) o[i][j] = 0.f;
    #pragma unroll
    for (int ks = 0; ks < 4; ks++) {
        int kc = ks * 8 + (lane & 3);
        unsigned a[4];
        a[0] = __float_as_uint(Ps[rbase * PHI_B_STR + kc]);
        a[1] = __float_as_uint(Ps[(rbase + 8) * PHI_B_STR + kc]);
        a[2] = __float_as_uint(Ps[rbase * PHI_B_STR + kc + 4]);
        a[3] = __float_as_uint(Ps[(rbase + 8) * PHI_B_STR + kc + 4]);
        #pragma unroll
        for (int fn = 0; fn < 8; fn++) {
            int cn = fn * 8 + (lane >> 2);
            unsigned bb[2];
            bb[0] = __float_as_uint(Kv[kc * AT_KV_STR + cn]);
            bb[1] = __float_as_uint(Kv[(kc + 4) * AT_KV_STR + cn]);
            mma_tf32(o[fn], a, bb);
        }
    }

    float z0 = Den[rbase];
    float z1 = Den[rbase + 8];
    size_t t0 = (size_t)(b * LL + tok0) + rbase;
    float* y0 = Y + t0 * DD + h * HDIM;
    float* y1 = Y + (t0 + 8) * DD + h * HDIM;
    #pragma unroll
    for (int fn = 0; fn < 8; fn++) {
        int cl = fn * 8 + 2 * (lane & 3);
        *(float2*)(y0 + cl) = make_float2(o[fn][0] * z0, o[fn][1] * z0);
        *(float2*)(y1 + cl) = make_float2(o[fn][2] * z1, o[fn][3] * z1);
    }
}

// ---------------------------------------------------------------------------
// Warp-per-row LayerNorm
// ---------------------------------------------------------------------------
__global__ __launch_bounds__(256) void ln_kernel(
    const float* __restrict__ in, const float* __restrict__ g,
    const float* __restrict__ b, float* __restrict__ out)
{
    int warp = threadIdx.x >> 5, lane = threadIdx.x & 31;
    size_t row = (size_t)blockIdx.x * 8 + warp;
    const float4* ip = (const float4*)(in + row * DD);

    float4 x[6];
    float s = 0.f, s2 = 0.f;
    #pragma unroll
    for (int i = 0; i < 6; i++) {
        x[i] = ip[lane + i * 32];
        s  += x[i].x + x[i].y + x[i].z + x[i].w;
        s2 += x[i].x * x[i].x + x[i].y * x[i].y
            + x[i].z * x[i].z + x[i].w * x[i].w;
    }
    #pragma unroll
    for (int off = 16; off > 0; off >>= 1) {
        s  += __shfl_xor_sync(0xFFFFFFFF, s,  off);
        s2 += __shfl_xor_sync(0xFFFFFFFF, s2, off);
    }
    float mu   = s * (1.0f / DD);
    float rstd = rsqrtf(s2 * (1.0f / DD) - mu * mu + LN_EPS);

    const float4* gp = (const float4*)g;
    const float4* bp = (const float4*)b;
    float4* op = (float4*)(out + row * DD);
    #pragma unroll
    for (int i = 0; i < 6; i++) {
        float4 gg = gp[lane + i * 32];
        float4 bb = bp[lane + i * 32];
        float4 o;
        o.x = (x[i].x - mu) * rstd * gg.x + bb.x;
        o.y = (x[i].y - mu) * rstd * gg.y + bb.y;
        o.z = (x[i].z - mu) * rstd * gg.z + bb.z;
        o.w = (x[i].w - mu) * rstd * gg.w + bb.w;
        op[lane + i * 32] = o;
    }
}

// ---------------------------------------------------------------------------
// Host orchestration
// ---------------------------------------------------------------------------
extern "C" void kernel_launch(void* const* d_in, const int* in_sizes, int n_in,
                              void* d_out, int out_size)
{
    const int*   idx     = (const int*)  d_in[0];
    const int*   mask    = (const int*)  d_in[1];
    const float* tok_emb = (const float*)d_in[2];
    const float* Wq = (const float*)d_in[3];
    const float* bq = (const float*)d_in[4];
    const float* Wk = (const float*)d_in[5];
    const float* bk = (const float*)d_in[6];
    const float* Wv = (const float*)d_in[7];
    const float* bv = (const float*)d_in[8];
    const float* Wo = (const float*)d_in[9];
    const float* bo = (const float*)d_in[10];
    const float* om = (const float*)d_in[11];
    const float* W1 = (const float*)d_in[12];
    const float* b1 = (const float*)d_in[13];
    const float* W2 = (const float*)d_in[14];
    const float* b2 = (const float*)d_in[15];
    const float* g1 = (const float*)d_in[16];
    const float* be1= (const float*)d_in[17];
    const float* g2 = (const float*)d_in[18];
    const float* be2= (const float*)d_in[19];
    const float* gf = (const float*)d_in[20];
    const float* bf = (const float*)d_in[21];
    float* out = (float*)d_out;

    float *X, *Y, *Q, *K, *V, *PHK, *KVP, *KSP, *COS, *SIN;
    cudaGetSymbolAddress((void**)&X,    g_X);
    cudaGetSymbolAddress((void**)&Y,    g_Y);
    cudaGetSymbolAddress((void**)&Q,    g_Q);
    cudaGetSymbolAddress((void**)&K,    g_K);
    cudaGetSymbolAddress((void**)&V,    g_V);
    cudaGetSymbolAddress((void**)&PHK,  g_PHK);
    cudaGetSymbolAddress((void**)&KVP,  g_KVP);
    cudaGetSymbolAddress((void**)&KSP,  g_KSP);
    cudaGetSymbolAddress((void**)&COS,  g_COS);
    cudaGetSymbolAddress((void**)&SIN,  g_SIN);

    cudaFuncSetAttribute(pgemm_kernel,
                         cudaFuncAttributeMaxDynamicSharedMemorySize, SMEM_GEMM);
    cudaFuncSetAttribute(qkv_gemm_kernel,
                         cudaFuncAttributeMaxDynamicSharedMemorySize, SMEM_GEMM);
    cudaFuncSetAttribute(phik_mma_kernel,
                         cudaFuncAttributeMaxDynamicSharedMemorySize, SMEM_PHI);
    cudaFuncSetAttribute(attn_fused_kernel,
                         cudaFuncAttributeMaxDynamicSharedMemorySize, SMEM_ATT);

    const size_t WMAT = (size_t)DD * DD;
    dim3 gGrid(DD / TN, NTOK / TM);       // (6, 256)
    dim3 qkvGrid(3 * DD / TN, NTOK / TM); // (18, 256)
    dim3 attGrid(LL / 128, NBH);          // (16, 192)

    rope_table_kernel<<<(LL * 32) / 256, 256>>>(COS, SIN);
    embed_kernel<<<(NTOK * DD / 4) / 256, 256>>>(idx, tok_emb, X);

    for (int i = 0; i < NLAYER; i++) {
        const float* om_i = om + (size_t)i * HDIM * FDIM;

        qkv_gemm_kernel<<<qkvGrid, 256, SMEM_GEMM>>>(
            X, Wq + i * WMAT, Wk + i * WMAT, Wv + i * WMAT,
            bq + i * DD, bk + i * DD, bv + i * DD, Q, K, V);

        phik_mma_kernel<<<(NTOK * HH) / 128, 256, SMEM_PHI>>>(
            K, om_i, COS, SIN, mask, PHK);

        kv_part_kernel<<<dim3(NBH, KVCH), 256>>>(PHK, V, KVP, KSP);

        attn_fused_kernel<<<attGrid, 256, SMEM_ATT>>>(
            Q, om_i, COS, SIN, KVP, KSP, Y);

        // X = Y @ Wo + bo + X
        pgemm_kernel<<<gGrid, 256, SMEM_GEMM>>>(Y, Wo + i * WMAT, bo + i * DD, X, X, 0);
        ln_kernel<<<NTOK / 8, 256>>>(X, g1 + i * DD, be1 + i * DD, X);
        // Q = gelu(X @ W1 + b1)
        pgemm_kernel<<<gGrid, 256, SMEM_GEMM>>>(X, W1 + i * WMAT, b1 + i * DD, nullptr, Q, 1);
        // Y = Q @ W2 + b2 + X
        pgemm_kernel<<<gGrid, 256, SMEM_GEMM>>>(Q, W2 + i * WMAT, b2 + i * DD, X, Y, 0);
        ln_kernel<<<NTOK / 8, 256>>>(Y, g2 + i * DD, be2 + i * DD, X);
    }

    ln_kernel<<<NTOK / 8, 256>>>(X, gf, bf, out);
}

// round 15
// speedup vs baseline: 1.0257x; 1.0133x over previous
#include <cuda_runtime.h>
#include <math.h>
#include <stdint.h>

// Problem constants
#define BB      16
#define LL      2048
#define DD      768
#define HH      12
#define NLAYER  4
#define FDIM    32
#define HDIM    64
#define NTOK    (BB * LL)            // 32768
#define ATTN_EPS 1e-6f
#define LN_EPS   1e-5f
#define NBH     (BB * HH)            // 192
#define KVCH    4                    // kv L-split chunks
#define NKV     (NBH * FDIM * HDIM)  // 393216
#define NKS     (NBH * FDIM)

// ---------------------------------------------------------------------------
// Scratch buffers
// ---------------------------------------------------------------------------
__device__ float g_X [(size_t)NTOK * DD];
__device__ float g_Y [(size_t)NTOK * DD];
__device__ float g_Q [(size_t)NTOK * DD];
__device__ float g_K [(size_t)NTOK * DD];
__device__ float g_V [(size_t)NTOK * DD];
__device__ float g_KVP [KVCH * NKV];
__device__ float g_KSP [KVCH * NKS];
__device__ float g_COS [LL * (HDIM / 2)];
__device__ float g_SIN [LL * (HDIM / 2)];

// ---------------------------------------------------------------------------
// PTX helpers
// ---------------------------------------------------------------------------
__device__ __forceinline__ void cpa16(uint32_t d, const void* s) {
    asm volatile("cp.async.cg.shared.global [%0], [%1], 16;" :: "r"(d), "l"(s));
}
#define CPA_COMMIT() asm volatile("cp.async.commit_group;" ::: "memory")
#define CPA_WAIT1()  asm volatile("cp.async.wait_group 1;" ::: "memory")

__device__ __forceinline__ uint32_t smem_u32(const void* p) {
    uint32_t a;
    asm("{ .reg .u64 t; cvta.to.shared.u64 t, %1; cvt.u32.u64 %0, t; }"
        : "=r"(a) : "l"(p));
    return a;
}

__device__ __forceinline__ float tf32_rna(float x) {
    unsigned r;
    asm("cvt.rna.tf32.f32 %0, %1;" : "=r"(r) : "f"(x));
    return __uint_as_float(r);
}

__device__ __forceinline__ void mma_tf32(float* c, const unsigned* a, const unsigned* b) {
    asm volatile(
        "mma.sync.aligned.m16n8k8.row.col.f32.tf32.tf32.f32 "
        "{%0,%1,%2,%3},{%4,%5,%6,%7},{%8,%9},{%0,%1,%2,%3};"
        : "+f"(c[0]), "+f"(c[1]), "+f"(c[2]), "+f"(c[3])
        : "r"(a[0]), "r"(a[1]), "r"(a[2]), "r"(a[3]), "r"(b[0]), "r"(b[1]));
}

// ---------------------------------------------------------------------------
// GEMM body (R4-proven shape): 128x128x32 tile, 8 warps of 64x32,
// cp.async 3-stage. Shared by pgemm_kernel and qkv_gemm_kernel.
// ---------------------------------------------------------------------------
#define TM 128
#define TN 128
#define TBK 32
#define NST 3
#define A_STR 36
#define B_STR 136
#define A_TILE_B (TM * A_STR * 4)           // 18432
#define B_TILE_B (TBK * B_STR * 4)          // 17408
#define STAGE_B  (A_TILE_B + B_TILE_B)      // 35840
#define OFF_BIAS (NST * STAGE_B)            // 107520
#define SMEM_GEMM (OFF_BIAS + TN * 4)       // 108032
#define NKT (DD / TBK)                      // 24

__device__ __forceinline__ void gemm_body(
    const float* __restrict__ A, const float* __restrict__ W,
    const float* __restrict__ bias, const float* __restrict__ R,
    float* __restrict__ C, int act, size_t row0, size_t col0, char* smem)
{
    uint32_t sb = smem_u32(smem);
    int tid = threadIdx.x, lane = tid & 31, warp = tid >> 5;
    int wm = (warp & 1) * 64;
    int wn = (warp >> 1) * 32;

    if (tid < TN) *(float*)(smem + OFF_BIAS + tid * 4) = bias[col0 + tid];

    int ar = tid >> 3, akc = tid & 7;
    int bk = tid >> 5, bnc = tid & 31;
    auto load_stage = [&](int u) {
        uint32_t st = sb + (u % NST) * STAGE_B;
        int k0 = u * TBK;
        #pragma unroll
        for (int i = 0; i < 4; i++) {
            int r = ar + i * 32;
            cpa16(st + r * (A_STR * 4) + akc * 16,
                  A + (row0 + r) * DD + k0 + akc * 4);
        }
        uint32_t bbase = st + A_TILE_B;
        #pragma unroll
        for (int i = 0; i < 4; i++) {
            int k = bk + i * 8;
            cpa16(bbase + k * (B_STR * 4) + bnc * 16,
                  W + (size_t)(k0 + k) * DD + col0 + bnc * 4);
        }
    };

    float acc[4][4][4];
    #pragma unroll
    for (int i = 0; i < 4; i++)
        #pragma unroll
        for (int j = 0; j < 4; j++)
            #pragma unroll
            for (int k = 0; k < 4; k++) acc[i][j][k] = 0.f;

    load_stage(0); CPA_COMMIT();
    load_stage(1); CPA_COMMIT();

    for (int t = 0; t < NKT; t++) {
        CPA_WAIT1();
        __syncthreads();
        if (t + 2 < NKT) load_stage(t + 2);
        CPA_COMMIT();
        const float* sA = (const float*)(smem + (t % NST) * STAGE_B);
        const float* sB = (const float*)(smem + (t % NST) * STAGE_B + A_TILE_B);
        #pragma unroll
        for (int ks = 0; ks < 4; ks++) {
            int kc = ks * 8 + (lane & 3);
            unsigned a[4][4], b[4][2];
            #pragma unroll
            for (int fm = 0; fm < 4; fm++) {
                int r = wm + fm * 16 + (lane >> 2);
                a[fm][0] = __float_as_uint(sA[r * A_STR + kc]);
                a[fm][1] = __float_as_uint(sA[(r + 8) * A_STR + kc]);
                a[fm][2] = __float_as_uint(sA[r * A_STR + kc + 4]);
                a[fm][3] = __float_as_uint(sA[(r + 8) * A_STR + kc + 4]);
            }
            #pragma unroll
            for (int fn = 0; fn < 4; fn++) {
                int cn = wn + fn * 8 + (lane >> 2);
                b[fn][0] = __float_as_uint(sB[kc * B_STR + cn]);
                b[fn][1] = __float_as_uint(sB[(kc + 4) * B_STR + cn]);
            }
            #pragma unroll
            for (int fm = 0; fm < 4; fm++)
                #pragma unroll
                for (int fn = 0; fn < 4; fn++)
                    mma_tf32(acc[fm][fn], a[fm], b[fn]);
        }
    }

    const float* sbias = (const float*)(smem + OFF_BIAS);
    #pragma unroll
    for (int fm = 0; fm < 4; fm++) {
        size_t r0 = row0 + wm + fm * 16 + (lane >> 2);
        size_t r1 = r0 + 8;
        #pragma unroll
        for (int fn = 0; fn < 4; fn++) {
            int cl = wn + fn * 8 + 2 * (lane & 3);
            size_t cn = col0 + cl;
            float bx = sbias[cl], by = sbias[cl + 1];
            float v0 = acc[fm][fn][0] + bx;
            float v1 = acc[fm][fn][1] + by;
            float v2 = acc[fm][fn][2] + bx;
            float v3 = acc[fm][fn][3] + by;
            if (act == 1) {
                v0 = 0.5f * v0 * (1.f + erff(v0 * 0.70710678118654752f));
                v1 = 0.5f * v1 * (1.f + erff(v1 * 0.70710678118654752f));
                v2 = 0.5f * v2 * (1.f + erff(v2 * 0.70710678118654752f));
                v3 = 0.5f * v3 * (1.f + erff(v3 * 0.70710678118654752f));
            }
            if (R) {
                float2 ra = *(const float2*)(R + r0 * DD + cn);
                float2 rb = *(const float2*)(R + r1 * DD + cn);
                v0 += ra.x; v1 += ra.y; v2 += rb.x; v3 += rb.y;
            }
            *(float2*)(C + r0 * DD + cn) = make_float2(v0, v1);
            *(float2*)(C + r1 * DD + cn) = make_float2(v2, v3);
        }
    }
}

__global__ __launch_bounds__(256, 2) void pgemm_kernel(
    const float* __restrict__ A, const float* __restrict__ W,
    const float* __restrict__ bias, const float* __restrict__ R,
    float* __restrict__ C, int act)
{
    extern __shared__ char smem[];
    gemm_body(A, W, bias, R, C, act,
              (size_t)blockIdx.y * TM, (size_t)blockIdx.x * TN, smem);
}

// Fused Q/K/V projection: grid.x = 18 (3 matrices x 6 col-blocks)
__global__ __launch_bounds__(256, 2) void qkv_gemm_kernel(
    const float* __restrict__ A,
    const float* __restrict__ Wq, const float* __restrict__ Wk,
    const float* __restrict__ Wv,
    const float* __restrict__ bq, const float* __restrict__ bk,
    const float* __restrict__ bv,
    float* __restrict__ Q, float* __restrict__ K, float* __restrict__ V)
{
    extern __shared__ char smem[];
    int mat = blockIdx.x / (DD / TN);
    int cb  = blockIdx.x % (DD / TN);
    const float* W  = (mat == 0) ? Wq : (mat == 1) ? Wk : Wv;
    const float* bi = (mat == 0) ? bq : (mat == 1) ? bk : bv;
    float*       C  = (mat == 0) ? Q  : (mat == 1) ? K  : V;
    gemm_body(A, W, bi, nullptr, C, 0,
              (size_t)blockIdx.y * TM, (size_t)cb * TN, smem);
}

// ---------------------------------------------------------------------------
// Embedding gather
// ---------------------------------------------------------------------------
__global__ __launch_bounds__(256) void embed_kernel(
    const int* __restrict__ idx, const float* __restrict__ emb,
    float* __restrict__ X)
{
    int i   = blockIdx.x * 256 + threadIdx.x;
    int tok = i / (DD / 4);
    int c4  = i % (DD / 4);
    const float4* src = (const float4*)(emb + (size_t)idx[tok] * DD);
    ((float4*)X)[i] = src[c4];
}

// ---------------------------------------------------------------------------
// Rotary cos/sin table
// ---------------------------------------------------------------------------
__global__ __launch_bounds__(256) void rope_table_kernel(
    float* __restrict__ cosT, float* __restrict__ sinT)
{
    int i = blockIdx.x * 256 + threadIdx.x;
    int j = i & 31;
    int l = i >> 5;
    double inv = pow(10000.0, -(double)(2 * j) / (double)HDIM);
    double fr  = (double)l * inv;
    cosT[i] = (float)cos(fr);
    sinT[i] = (float)sin(fr);
}

// ---------------------------------------------------------------------------
// Fused phi(K) + KV contraction: per (bh, L-chunk) block.
//   phk = relu(rot(K) @ omega) * mask        (tensor MMA, smem-resident)
//   KVP[bh,ch] = phk^T @ V                    (tensor MMA, K=tokens)
//   KSP[bh,ch] = colsum(phk)
// PHK is never materialized in global memory.
// ---------------------------------------------------------------------------
#define PKV_AV_STR 72
#define PKV_A_STR  68
#define PKV_PS_STR 40
#define PKV_OFF_PS (128 * PKV_AV_STR)                  // 9216 floats
#define PKV_OFF_OM (PKV_OFF_PS + 128 * PKV_PS_STR)     // 14336
#define PKV_OFF_KS (PKV_OFF_OM + HDIM * PKV_PS_STR)    // 16896
#define SMEM_PKV   ((PKV_OFF_KS + 256) * 4)            // 68608 bytes

__global__ __launch_bounds__(256, 2) void phikv_kernel(
    const float* __restrict__ K, const float* __restrict__ V,
    const float* __restrict__ omega,
    const float* __restrict__ cosT, const float* __restrict__ sinT,
    const int* __restrict__ mask,
    float* __restrict__ KVP, float* __restrict__ KSP)
{
    extern __shared__ float sm[];
    float* AV  = sm;                     // K-rot (stride 68) / V (stride 72)
    float* Ps  = sm + PKV_OFF_PS;        // [l][40] phi values (tf32)
    float* Om  = sm + PKV_OFF_OM;        // [d][40]
    float* Kss = sm + PKV_OFF_KS;        // [8][32]

    int tid = threadIdx.x, lane = tid & 31, warp = tid >> 5;
    int bh = blockIdx.x, ch = blockIdx.y;
    int b = bh / HH, h = bh % HH;
    int lbase = ch * (LL / KVCH);        // 512-token chunk

    // omega -> smem tf32
    {
        int i0 = tid * 8;
        #pragma unroll
        for (int u = 0; u < 2; u++) {
            int i = i0 + u * 4;
            float4 v = *(const float4*)(omega + i);
            int d = i >> 5, f = i & 31;
            Om[d * PKV_PS_STR + f + 0] = tf32_rna(v.x);
            Om[d * PKV_PS_STR + f + 1] = tf32_rna(v.y);
            Om[d * PKV_PS_STR + f + 2] = tf32_rna(v.z);
            Om[d * PKV_PS_STR + f + 3] = tf32_rna(v.w);
        }
    }

    float kvacc[2][4];
    #pragma unroll
    for (int i = 0; i < 2; i++)
        #pragma unroll
        for (int j = 0; j < 4; j++) kvacc[i][j] = 0.f;
    float ksacc = 0.f;

    for (int st = 0; st < 4; st++) {
        int l0 = lbase + st * 128;

        // 1. load + rotate K rows -> AV (stride 68, tf32)
        {
            int row = tid >> 1;
            int j0  = (tid & 1) * 16;
            int l   = l0 + row;
            const float* xp = K + ((size_t)(b * LL) + l) * DD + h * HDIM;
            #pragma unroll
            for (int jj = 0; jj < 4; jj++) {
                int j = j0 + jj * 4;
                float4 x1 = *(const float4*)(xp + j);
                float4 x2 = *(const float4*)(xp + j + 32);
                float4 c  = *(const float4*)(cosT + l * 32 + j);
                float4 s  = *(const float4*)(sinT + l * 32 + j);
                float* a1 = AV + row * PKV_A_STR + j;
                a1[0]  = tf32_rna(x1.x * c.x - x2.x * s.x);
                a1[32] = tf32_rna(x2.x * c.x + x1.x * s.x);
                a1[1]  = tf32_rna(x1.y * c.y - x2.y * s.y);
                a1[33] = tf32_rna(x2.y * c.y + x1.y * s.y);
                a1[2]  = tf32_rna(x1.z * c.z - x2.z * s.z);
                a1[34] = tf32_rna(x2.z * c.z + x1.z * s.z);
                a1[3]  = tf32_rna(x1.w * c.w - x2.w * s.w);
                a1[35] = tf32_rna(x2.w * c.w + x1.w * s.w);
            }
        }
        __syncthreads();

        // 2. phi MMA -> Ps (masked relu, tf32)
        {
            int rbase = warp * 16 + (lane >> 2);
            float p[4][4];
            #pragma unroll
            for (int i = 0; i < 4; i++)
                #pragma unroll
                for (int j = 0; j < 4; j++) p[i][j] = 0.f;
            #pragma unroll
            for (int ks = 0; ks < 8; ks++) {
                int kc = ks * 8 + (lane & 3);
                unsigned a[4];
                a[0] = __float_as_uint(AV[rbase * PKV_A_STR + kc]);
                a[1] = __float_as_uint(AV[(rbase + 8) * PKV_A_STR + kc]);
                a[2] = __float_as_uint(AV[rbase * PKV_A_STR + kc + 4]);
                a[3] = __float_as_uint(AV[(rbase + 8) * PKV_A_STR + kc + 4]);
                #pragma unroll
                for (int fn = 0; fn < 4; fn++) {
                    int cn = fn * 8 + (lane >> 2);
                    unsigned bb[2];
                    bb[0] = __float_as_uint(Om[kc * PKV_PS_STR + cn]);
                    bb[1] = __float_as_uint(Om[(kc + 4) * PKV_PS_STR + cn]);
                    mma_tf32(p[fn], a, bb);
                }
            }
            float m0 = (float)mask[b * LL + l0 + rbase];
            float m1 = (float)mask[b * LL + l0 + rbase + 8];
            #pragma unroll
            for (int fn = 0; fn < 4; fn++) {
                int cl = fn * 8 + 2 * (lane & 3);
                Ps[rbase * PKV_PS_STR + cl]           = tf32_rna(fmaxf(p[fn][0], 0.f) * m0);
                Ps[rbase * PKV_PS_STR + cl + 1]       = tf32_rna(fmaxf(p[fn][1], 0.f) * m0);
                Ps[(rbase + 8) * PKV_PS_STR + cl]     = tf32_rna(fmaxf(p[fn][2], 0.f) * m1);
                Ps[(rbase + 8) * PKV_PS_STR + cl + 1] = tf32_rna(fmaxf(p[fn][3], 0.f) * m1);
            }
        }
        __syncthreads();

        // 3. ksum partial + load V -> AV (stride 72, tf32)
        {
            int f = tid & 31, grp = tid >> 5;
            float s = 0.f;
            #pragma unroll
            for (int r = 0; r < 16; r++)
                s += Ps[(grp * 16 + r) * PKV_PS_STR + f];
            ksacc += s;
        }
        {
            int row = tid >> 1;
            int c0  = (tid & 1) * 32;
            const float* vp = V + ((size_t)(b * LL) + l0 + row) * DD + h * HDIM + c0;
            float* dst = AV + row * PKV_AV_STR + c0;
            #pragma unroll
            for (int i = 0; i < 8; i++) {
                float4 v = *(const float4*)(vp + i * 4);
                dst[i * 4 + 0] = tf32_rna(v.x);
                dst[i * 4 + 1] = tf32_rna(v.y);
                dst[i * 4 + 2] = tf32_rna(v.z);
                dst[i * 4 + 3] = tf32_rna(v.w);
            }
        }
        __syncthreads();

        // 4. kv MMA: KV[f][d] += sum_l phk[l][f] * V[l][d]
        //    warp -> d cols [warp*8, warp*8+8), fm over f {0-15,16-31}
        {
            int cn = warp * 8 + (lane >> 2);
            #pragma unroll
            for (int ks = 0; ks < 16; ks++) {
                int kc = ks * 8 + (lane & 3);
                unsigned bb[2];
                bb[0] = __float_as_uint(AV[kc * PKV_AV_STR + cn]);
                bb[1] = __float_as_uint(AV[(kc + 4) * PKV_AV_STR + cn]);
                #pragma unroll
                for (int fm = 0; fm < 2; fm++) {
                    int r = fm * 16 + (lane >> 2);
                    unsigned a[4];
                    a[0] = __float_as_uint(Ps[kc * PKV_PS_STR + r]);
                    a[1] = __float_as_uint(Ps[kc * PKV_PS_STR + r + 8]);
                    a[2] = __float_as_uint(Ps[(kc + 4) * PKV_PS_STR + r]);
                    a[3] = __float_as_uint(Ps[(kc + 4) * PKV_PS_STR + r + 8]);
                    mma_tf32(kvacc[fm], a, bb);
                }
            }
        }
        __syncthreads();   // AV/Ps reuse guard for next subtile
    }

    // write KVP partial
    {
        size_t base = ((size_t)(ch * NBH + bh)) * FDIM * HDIM;
        #pragma unroll
        for (int fm = 0; fm < 2; fm++) {
            int f0 = fm * 16 + (lane >> 2);
            int d0 = warp * 8 + 2 * (lane & 3);
            *(float2*)(KVP + base + (size_t)f0 * HDIM + d0) =
                make_float2(kvacc[fm][0], kvacc[fm][1]);
            *(float2*)(KVP + base + (size_t)(f0 + 8) * HDIM + d0) =
                make_float2(kvacc[fm][2], kvacc[fm][3]);
        }
    }
    // write KSP partial
    Kss[tid] = ksacc;
    __syncthreads();
    if (tid < FDIM) {
        float s = 0.f;
        #pragma unroll
        for (int g = 0; g < 8; g++) s += Kss[g * 32 + tid];
        KSP[(size_t)(ch * NBH + bh) * FDIM + tid] = s;
    }
}

// ---------------------------------------------------------------------------
// Fused attention output: Y = (relu(rot(Q)@omega) @ KV) * z
// KV/KSUM reduced from the 4 partial buffers during the load phase.
// ---------------------------------------------------------------------------
#define PHI_A_STR 68
#define PHI_B_STR 40
#define AT_KV_STR 72
#define AT_OFF_PS  (128 * PHI_A_STR)
#define AT_OFF_OM  (AT_OFF_PS + 128 * PHI_B_STR)
#define AT_OFF_KV  (AT_OFF_OM + HDIM * PHI_B_STR)
#define AT_OFF_DEN (AT_OFF_KV + FDIM * AT_KV_STR)
#define AT_OFF_KSM (AT_OFF_DEN + 128)
#define SMEM_ATT   ((AT_OFF_KSM + FDIM) * 4)          // 75392 bytes

__global__ __launch_bounds__(256, 2) void attn_fused_kernel(
    const float* __restrict__ Q, const float* __restrict__ omega,
    const float* __restrict__ cosT, const float* __restrict__ sinT,
    const float* __restrict__ KVP, const float* __restrict__ KSP,
    float* __restrict__ Y)
{
    extern __shared__ float sm[];
    float* As  = sm;
    float* Ps  = sm + AT_OFF_PS;
    float* Om  = sm + AT_OFF_OM;
    float* Kv  = sm + AT_OFF_KV;
    float* Den = sm + AT_OFF_DEN;
    float* Ksm = sm + AT_OFF_KSM;

    int tid = threadIdx.x, lane = tid & 31, warp = tid >> 5;
    int bh = blockIdx.y;
    int b  = bh / HH, h = bh % HH;
    int tok0 = blockIdx.x * 128;

    {
        int i0 = tid * 8;
        #pragma unroll
        for (int u = 0; u < 2; u++) {
            int i = i0 + u * 4;
            float4 v = *(const float4*)(omega + i);
            int d = i >> 5, f = i & 31;
            Om[d * PHI_B_STR + f + 0] = tf32_rna(v.x);
            Om[d * PHI_B_STR + f + 1] = tf32_rna(v.y);
            Om[d * PHI_B_STR + f + 2] = tf32_rna(v.z);
            Om[d * PHI_B_STR + f + 3] = tf32_rna(v.w);
        }
    }
    {
        const float* kv0 = KVP + (size_t)bh * FDIM * HDIM;
        int i0 = tid * 8;
        #pragma unroll
        for (int u = 0; u < 2; u++) {
            int i = i0 + u * 4;
            float4 v0 = *(const float4*)(kv0 + i);
            float4 v1 = *(const float4*)(kv0 + NKV + i);
            float4 v2 = *(const float4*)(kv0 + 2 * (size_t)NKV + i);
            float4 v3 = *(const float4*)(kv0 + 3 * (size_t)NKV + i);
            float4 v;
            v.x = v0.x + v1.x + v2.x + v3.x;
            v.y = v0.y + v1.y + v2.y + v3.y;
            v.z = v0.z + v1.z + v2.z + v3.z;
            v.w = v0.w + v1.w + v2.w + v3.w;
            int f = i >> 6, d = i & 63;
            *(float4*)&Kv[f * AT_KV_STR + d] = v;
        }
    }
    if (tid < FDIM) {
        int i = bh * FDIM + tid;
        Ksm[tid] = KSP[i] + KSP[NKS + i] + KSP[2 * NKS + i] + KSP[3 * NKS + i];
    }

    {
        int row = tid >> 1;
        int j0  = (tid & 1) * 16;
        int l   = tok0 + row;
        const float* xp = Q + ((size_t)(b * LL) + l) * DD + h * HDIM;
        #pragma unroll
        for (int jj = 0; jj < 4; jj++) {
            int j = j0 + jj * 4;
            float4 x1 = *(const float4*)(xp + j);
            float4 x2 = *(const float4*)(xp + j + 32);
            float4 c  = *(const float4*)(cosT + l * 32 + j);
            float4 s  = *(const float4*)(sinT + l * 32 + j);
            float* a1 = As + row * PHI_A_STR + j;
            a1[0]  = tf32_rna(x1.x * c.x - x2.x * s.x);
            a1[32] = tf32_rna(x2.x * c.x + x1.x * s.x);
            a1[1]  = tf32_rna(x1.y * c.y - x2.y * s.y);
            a1[33] = tf32_rna(x2.y * c.y + x1.y * s.y);
            a1[2]  = tf32_rna(x1.z * c.z - x2.z * s.z);
            a1[34] = tf32_rna(x2.z * c.z + x1.z * s.z);
            a1[3]  = tf32_rna(x1.w * c.w - x2.w * s.w);
            a1[35] = tf32_rna(x2.w * c.w + x1.w * s.w);
        }
    }
    __syncthreads();

    int rbase = warp * 16 + (lane >> 2);

    {
        float p[4][4];
        #pragma unroll
        for (int i = 0; i < 4; i++)
            #pragma unroll
            for (int j = 0; j < 4; j++) p[i][j] = 0.f;
        #pragma unroll
        for (int ks = 0; ks < 8; ks++) {
            int kc = ks * 8 + (lane & 3);
            unsigned a[4];
            a[0] = __float_as_uint(As[rbase * PHI_A_STR + kc]);
            a[1] = __float_as_uint(As[(rbase + 8) * PHI_A_STR + kc]);
            a[2] = __float_as_uint(As[rbase * PHI_A_STR + kc + 4]);
            a[3] = __float_as_uint(As[(rbase + 8) * PHI_A_STR + kc + 4]);
            #pragma unroll
            for (int fn = 0; fn < 4; fn++) {
                int cn = fn * 8 + (lane >> 2);
                unsigned bb[2];
                bb[0] = __float_as_uint(Om[kc * PHI_B_STR + cn]);
                bb[1] = __float_as_uint(Om[(kc + 4) * PHI_B_STR + cn]);
                mma_tf32(p[fn], a, bb);
            }
        }
        #pragma unroll
        for (int fn = 0; fn < 4; fn++) {
            int cl = fn * 8 + 2 * (lane & 3);
            Ps[rbase * PHI_B_STR + cl]           = fmaxf(p[fn][0], 0.f);
            Ps[rbase * PHI_B_STR + cl + 1]       = fmaxf(p[fn][1], 0.f);
            Ps[(rbase + 8) * PHI_B_STR + cl]     = fmaxf(p[fn][2], 0.f);
            Ps[(rbase + 8) * PHI_B_STR + cl + 1] = fmaxf(p[fn][3], 0.f);
        }
    }
    __syncthreads();

    if (tid < 128) {
        float s = ATTN_EPS;
        #pragma unroll
        for (int f = 0; f < FDIM; f++) s += Ps[tid * PHI_B_STR + f] * Ksm[f];
        Den[tid] = 1.0f / s;
    }
    __syncthreads();

    float o[8][4];
    #pragma unroll
    for (int i = 0; i < 8; i++)
        #pragma unroll
        for (int j = 0; j < 4; j++) o[i][j] = 0.f;
    #pragma unroll
    for (int ks = 0; ks < 4; ks++) {
        int kc = ks * 8 + (lane & 3);
        unsigned a[4];
        a[0] = __float_as_uint(Ps[rbase * PHI_B_STR + kc]);
        a[1] = __float_as_uint(Ps[(rbase + 8) * PHI_B_STR + kc]);
        a[2] = __float_as_uint(Ps[rbase * PHI_B_STR + kc + 4]);
        a[3] = __float_as_uint(Ps[(rbase + 8) * PHI_B_STR + kc + 4]);
        #pragma unroll
        for (int fn = 0; fn < 8; fn++) {
            int cn = fn * 8 + (lane >> 2);
            unsigned bb[2];
            bb[0] = __float_as_uint(Kv[kc * AT_KV_STR + cn]);
            bb[1] = __float_as_uint(Kv[(kc + 4) * AT_KV_STR + cn]);
            mma_tf32(o[fn], a, bb);
        }
    }

    float z0 = Den[rbase];
    float z1 = Den[rbase + 8];
    size_t t0 = (size_t)(b * LL + tok0) + rbase;
    float* y0 = Y + t0 * DD + h * HDIM;
    float* y1 = Y + (t0 + 8) * DD + h * HDIM;
    #pragma unroll
    for (int fn = 0; fn < 8; fn++) {
        int cl = fn * 8 + 2 * (lane & 3);
        *(float2*)(y0 + cl) = make_float2(o[fn][0] * z0, o[fn][1] * z0);
        *(float2*)(y1 + cl) = make_float2(o[fn][2] * z1, o[fn][3] * z1);
    }
}

// ---------------------------------------------------------------------------
// Warp-per-row LayerNorm
// ---------------------------------------------------------------------------
__global__ __launch_bounds__(256) void ln_kernel(
    const float* __restrict__ in, const float* __restrict__ g,
    const float* __restrict__ b, float* __restrict__ out)
{
    int warp = threadIdx.x >> 5, lane = threadIdx.x & 31;
    size_t row = (size_t)blockIdx.x * 8 + warp;
    const float4* ip = (const float4*)(in + row * DD);

    float4 x[6];
    float s = 0.f, s2 = 0.f;
    #pragma unroll
    for (int i = 0; i < 6; i++) {
        x[i] = ip[lane + i * 32];
        s  += x[i].x + x[i].y + x[i].z + x[i].w;
        s2 += x[i].x * x[i].x + x[i].y * x[i].y
            + x[i].z * x[i].z + x[i].w * x[i].w;
    }
    #pragma unroll
    for (int off = 16; off > 0; off >>= 1) {
        s  += __shfl_xor_sync(0xFFFFFFFF, s,  off);
        s2 += __shfl_xor_sync(0xFFFFFFFF, s2, off);
    }
    float mu   = s * (1.0f / DD);
    float rstd = rsqrtf(s2 * (1.0f / DD) - mu * mu + LN_EPS);

    const float4* gp = (const float4*)g;
    const float4* bp = (const float4*)b;
    float4* op = (float4*)(out + row * DD);
    #pragma unroll
    for (int i = 0; i < 6; i++) {
        float4 gg = gp[lane + i * 32];
        float4 bb = bp[lane + i * 32];
        float4 o;
        o.x = (x[i].x - mu) * rstd * gg.x + bb.x;
        o.y = (x[i].y - mu) * rstd * gg.y + bb.y;
        o.z = (x[i].z - mu) * rstd * gg.z + bb.z;
        o.w = (x[i].w - mu) * rstd * gg.w + bb.w;
        op[lane + i * 32] = o;
    }
}

// ---------------------------------------------------------------------------
// Host orchestration
// ---------------------------------------------------------------------------
extern "C" void kernel_launch(void* const* d_in, const int* in_sizes, int n_in,
                              void* d_out, int out_size)
{
    const int*   idx     = (const int*)  d_in[0];
    const int*   mask    = (const int*)  d_in[1];
    const float* tok_emb = (const float*)d_in[2];
    const float* Wq = (const float*)d_in[3];
    const float* bq = (const float*)d_in[4];
    const float* Wk = (const float*)d_in[5];
    const float* bk = (const float*)d_in[6];
    const float* Wv = (const float*)d_in[7];
    const float* bv = (const float*)d_in[8];
    const float* Wo = (const float*)d_in[9];
    const float* bo = (const float*)d_in[10];
    const float* om = (const float*)d_in[11];
    const float* W1 = (const float*)d_in[12];
    const float* b1 = (const float*)d_in[13];
    const float* W2 = (const float*)d_in[14];
    const float* b2 = (const float*)d_in[15];
    const float* g1 = (const float*)d_in[16];
    const float* be1= (const float*)d_in[17];
    const float* g2 = (const float*)d_in[18];
    const float* be2= (const float*)d_in[19];
    const float* gf = (const float*)d_in[20];
    const float* bf = (const float*)d_in[21];
    float* out = (float*)d_out;

    float *X, *Y, *Q, *K, *V, *KVP, *KSP, *COS, *SIN;
    cudaGetSymbolAddress((void**)&X,    g_X);
    cudaGetSymbolAddress((void**)&Y,    g_Y);
    cudaGetSymbolAddress((void**)&Q,    g_Q);
    cudaGetSymbolAddress((void**)&K,    g_K);
    cudaGetSymbolAddress((void**)&V,    g_V);
    cudaGetSymbolAddress((void**)&KVP,  g_KVP);
    cudaGetSymbolAddress((void**)&KSP,  g_KSP);
    cudaGetSymbolAddress((void**)&COS,  g_COS);
    cudaGetSymbolAddress((void**)&SIN,  g_SIN);

    cudaFuncSetAttribute(pgemm_kernel,
                         cudaFuncAttributeMaxDynamicSharedMemorySize, SMEM_GEMM);
    cudaFuncSetAttribute(qkv_gemm_kernel,
                         cudaFuncAttributeMaxDynamicSharedMemorySize, SMEM_GEMM);
    cudaFuncSetAttribute(phikv_kernel,
                         cudaFuncAttributeMaxDynamicSharedMemorySize, SMEM_PKV);
    cudaFuncSetAttribute(attn_fused_kernel,
                         cudaFuncAttributeMaxDynamicSharedMemorySize, SMEM_ATT);

    const size_t WMAT = (size_t)DD * DD;
    dim3 gGrid(DD / TN, NTOK / TM);       // (6, 256)
    dim3 qkvGrid(3 * DD / TN, NTOK / TM); // (18, 256)
    dim3 attGrid(LL / 128, NBH);          // (16, 192)

    rope_table_kernel<<<(LL * 32) / 256, 256>>>(COS, SIN);
    embed_kernel<<<(NTOK * DD / 4) / 256, 256>>>(idx, tok_emb, X);

    for (int i = 0; i < NLAYER; i++) {
        const float* om_i = om + (size_t)i * HDIM * FDIM;

        qkv_gemm_kernel<<<qkvGrid, 256, SMEM_GEMM>>>(
            X, Wq + i * WMAT, Wk + i * WMAT, Wv + i * WMAT,
            bq + i * DD, bk + i * DD, bv + i * DD, Q, K, V);

        phikv_kernel<<<dim3(NBH, KVCH), 256, SMEM_PKV>>>(
            K, V, om_i, COS, SIN, mask, KVP, KSP);

        attn_fused_kernel<<<attGrid, 256, SMEM_ATT>>>(
            Q, om_i, COS, SIN, KVP, KSP, Y);

        // X = Y @ Wo + bo + X
        pgemm_kernel<<<gGrid, 256, SMEM_GEMM>>>(Y, Wo + i * WMAT, bo + i * DD, X, X, 0);
        ln_kernel<<<NTOK / 8, 256>>>(X, g1 + i * DD, be1 + i * DD, X);
        // Q = gelu(X @ W1 + b1)
        pgemm_kernel<<<gGrid, 256, SMEM_GEMM>>>(X, W1 + i * WMAT, b1 + i * DD, nullptr, Q, 1);
        // Y = Q @ W2 + b2 + X
        pgemm_kernel<<<gGrid, 256, SMEM_GEMM>>>(Q, W2 + i * WMAT, b2 + i * DD, X, Y, 0);
        ln_kernel<<<NTOK / 8, 256>>>(Y, g2 + i * DD, be2 + i * DD, X);
    }

    ln_kernel<<<NTOK / 8, 256>>>(X, gf, bf, out);
}

// round 16
// speedup vs baseline: 1.0504x; 1.0241x over previous
#include <cuda_runtime.h>
#include <math.h>
#include <stdint.h>

// Problem constants
#define BB      16
#define LL      2048
#define DD      768
#define HH      12
#define NLAYER  4
#define FDIM    32
#define HDIM    64
#define NTOK    (BB * LL)            // 32768
#define ATTN_EPS 1e-6f
#define LN_EPS   1e-5f
#define NBH     (BB * HH)            // 192
#define KVCH    4                    // kv L-split chunks
#define NKV     (NBH * FDIM * HDIM)  // 393216
#define NKS     (NBH * FDIM)

// ---------------------------------------------------------------------------
// Scratch buffers
// ---------------------------------------------------------------------------
__device__ float g_X [(size_t)NTOK * DD];
__device__ float g_Y [(size_t)NTOK * DD];
__device__ float g_Q [(size_t)NTOK * DD];
__device__ float g_K [(size_t)NTOK * DD];
__device__ float g_V [(size_t)NTOK * DD];
__device__ float g_KVP [KVCH * NKV];
__device__ float g_KSP [KVCH * NKS];
__device__ float g_COS [LL * (HDIM / 2)];
__device__ float g_SIN [LL * (HDIM / 2)];

// ---------------------------------------------------------------------------
// PTX helpers
// ---------------------------------------------------------------------------
__device__ __forceinline__ void cpa16(uint32_t d, const void* s) {
    asm volatile("cp.async.cg.shared.global [%0], [%1], 16;" :: "r"(d), "l"(s));
}
#define CPA_COMMIT() asm volatile("cp.async.commit_group;" ::: "memory")
#define CPA_WAIT1()  asm volatile("cp.async.wait_group 1;" ::: "memory")

__device__ __forceinline__ uint32_t smem_u32(const void* p) {
    uint32_t a;
    asm("{ .reg .u64 t; cvta.to.shared.u64 t, %1; cvt.u32.u64 %0, t; }"
        : "=r"(a) : "l"(p));
    return a;
}

__device__ __forceinline__ float tf32_rna(float x) {
    unsigned r;
    asm("cvt.rna.tf32.f32 %0, %1;" : "=r"(r) : "f"(x));
    return __uint_as_float(r);
}

__device__ __forceinline__ void mma_tf32(float* c, const unsigned* a, const unsigned* b) {
    asm volatile(
        "mma.sync.aligned.m16n8k8.row.col.f32.tf32.tf32.f32 "
        "{%0,%1,%2,%3},{%4,%5,%6,%7},{%8,%9},{%0,%1,%2,%3};"
        : "+f"(c[0]), "+f"(c[1]), "+f"(c[2]), "+f"(c[3])
        : "r"(a[0]), "r"(a[1]), "r"(a[2]), "r"(a[3]), "r"(b[0]), "r"(b[1]));
}

// ---------------------------------------------------------------------------
// GEMM: 128x128x32 tile, 8 warps of 64x32, cp.async 3-stage.
// k-slot permutation: logical slot (q,p) -> physical k = ks*8 + 2q + p,
// making A fragment pairs adjacent -> LDS.64 (halves A-side load instrs).
// A stride 40: float2 bank = 4*(lane>>2)+q  (bijective per half-warp)
// B stride 132: bank = 8q + (lane>>2) + c   (32 distinct, full warp)
// ---------------------------------------------------------------------------
#define TM 128
#define TN 128
#define TBK 32
#define NST 3
#define A_STR 40
#define B_STR 132
#define A_TILE_B (TM * A_STR * 4)           // 20480
#define B_TILE_B (TBK * B_STR * 4)          // 16896
#define STAGE_B  (A_TILE_B + B_TILE_B)      // 37376
#define OFF_BIAS (NST * STAGE_B)            // 112128
#define SMEM_GEMM (OFF_BIAS + TN * 4)       // 112640
#define NKT (DD / TBK)                      // 24

__device__ __forceinline__ void gemm_body(
    const float* __restrict__ A, const float* __restrict__ W,
    const float* __restrict__ bias, const float* __restrict__ R,
    float* __restrict__ C, int act, size_t row0, size_t col0, char* smem)
{
    uint32_t sb = smem_u32(smem);
    int tid = threadIdx.x, lane = tid & 31, warp = tid >> 5;
    int wm = (warp & 1) * 64;
    int wn = (warp >> 1) * 32;

    if (tid < TN) *(float*)(smem + OFF_BIAS + tid * 4) = bias[col0 + tid];

    int ar = tid >> 3, akc = tid & 7;
    int bk = tid >> 5, bnc = tid & 31;
    auto load_stage = [&](int u) {
        uint32_t st = sb + (u % NST) * STAGE_B;
        int k0 = u * TBK;
        #pragma unroll
        for (int i = 0; i < 4; i++) {
            int r = ar + i * 32;
            cpa16(st + r * (A_STR * 4) + akc * 16,
                  A + (row0 + r) * DD + k0 + akc * 4);
        }
        uint32_t bbase = st + A_TILE_B;
        #pragma unroll
        for (int i = 0; i < 4; i++) {
            int k = bk + i * 8;
            cpa16(bbase + k * (B_STR * 4) + bnc * 16,
                  W + (size_t)(k0 + k) * DD + col0 + bnc * 4);
        }
    };

    float acc[4][4][4];
    #pragma unroll
    for (int i = 0; i < 4; i++)
        #pragma unroll
        for (int j = 0; j < 4; j++)
            #pragma unroll
            for (int k = 0; k < 4; k++) acc[i][j][k] = 0.f;

    load_stage(0); CPA_COMMIT();
    load_stage(1); CPA_COMMIT();

    for (int t = 0; t < NKT; t++) {
        CPA_WAIT1();
        __syncthreads();
        if (t + 2 < NKT) load_stage(t + 2);
        CPA_COMMIT();
        const float* sA = (const float*)(smem + (t % NST) * STAGE_B);
        const float* sB = (const float*)(smem + (t % NST) * STAGE_B + A_TILE_B);
        #pragma unroll
        for (int ks = 0; ks < 4; ks++) {
            int kp = ks * 8 + 2 * (lane & 3);   // physical k, slot p=0
            unsigned a[4][4], b[4][2];
            #pragma unroll
            for (int fm = 0; fm < 4; fm++) {
                int r = wm + fm * 16 + (lane >> 2);
                float2 lo = *(const float2*)&sA[r * A_STR + kp];
                float2 hi = *(const float2*)&sA[(r + 8) * A_STR + kp];
                a[fm][0] = __float_as_uint(lo.x);
                a[fm][1] = __float_as_uint(hi.x);
                a[fm][2] = __float_as_uint(lo.y);
                a[fm][3] = __float_as_uint(hi.y);
            }
            #pragma unroll
            for (int fn = 0; fn < 4; fn++) {
                int cn = wn + fn * 8 + (lane >> 2);
                b[fn][0] = __float_as_uint(sB[kp * B_STR + cn]);
                b[fn][1] = __float_as_uint(sB[(kp + 1) * B_STR + cn]);
            }
            #pragma unroll
            for (int fm = 0; fm < 4; fm++)
                #pragma unroll
                for (int fn = 0; fn < 4; fn++)
                    mma_tf32(acc[fm][fn], a[fm], b[fn]);
        }
    }

    const float* sbias = (const float*)(smem + OFF_BIAS);
    #pragma unroll
    for (int fm = 0; fm < 4; fm++) {
        size_t r0 = row0 + wm + fm * 16 + (lane >> 2);
        size_t r1 = r0 + 8;
        #pragma unroll
        for (int fn = 0; fn < 4; fn++) {
            int cl = wn + fn * 8 + 2 * (lane & 3);
            size_t cn = col0 + cl;
            float bx = sbias[cl], by = sbias[cl + 1];
            float v0 = acc[fm][fn][0] + bx;
            float v1 = acc[fm][fn][1] + by;
            float v2 = acc[fm][fn][2] + bx;
            float v3 = acc[fm][fn][3] + by;
            if (act == 1) {
                v0 = 0.5f * v0 * (1.f + erff(v0 * 0.70710678118654752f));
                v1 = 0.5f * v1 * (1.f + erff(v1 * 0.70710678118654752f));
                v2 = 0.5f * v2 * (1.f + erff(v2 * 0.70710678118654752f));
                v3 = 0.5f * v3 * (1.f + erff(v3 * 0.70710678118654752f));
            }
            if (R) {
                float2 ra = *(const float2*)(R + r0 * DD + cn);
                float2 rb = *(const float2*)(R + r1 * DD + cn);
                v0 += ra.x; v1 += ra.y; v2 += rb.x; v3 += rb.y;
            }
            *(float2*)(C + r0 * DD + cn) = make_float2(v0, v1);
            *(float2*)(C + r1 * DD + cn) = make_float2(v2, v3);
        }
    }
}

__global__ __launch_bounds__(256, 2) void pgemm_kernel(
    const float* __restrict__ A, const float* __restrict__ W,
    const float* __restrict__ bias, const float* __restrict__ R,
    float* __restrict__ C, int act)
{
    extern __shared__ char smem[];
    gemm_body(A, W, bias, R, C, act,
              (size_t)blockIdx.y * TM, (size_t)blockIdx.x * TN, smem);
}

// Fused Q/K/V projection: grid.x = 18 (3 matrices x 6 col-blocks)
__global__ __launch_bounds__(256, 2) void qkv_gemm_kernel(
    const float* __restrict__ A,
    const float* __restrict__ Wq, const float* __restrict__ Wk,
    const float* __restrict__ Wv,
    const float* __restrict__ bq, const float* __restrict__ bk,
    const float* __restrict__ bv,
    float* __restrict__ Q, float* __restrict__ K, float* __restrict__ V)
{
    extern __shared__ char smem[];
    int mat = blockIdx.x / (DD / TN);
    int cb  = blockIdx.x % (DD / TN);
    const float* W  = (mat == 0) ? Wq : (mat == 1) ? Wk : Wv;
    const float* bi = (mat == 0) ? bq : (mat == 1) ? bk : bv;
    float*       C  = (mat == 0) ? Q  : (mat == 1) ? K  : V;
    gemm_body(A, W, bi, nullptr, C, 0,
              (size_t)blockIdx.y * TM, (size_t)cb * TN, smem);
}

// ---------------------------------------------------------------------------
// Embedding gather
// ---------------------------------------------------------------------------
__global__ __launch_bounds__(256) void embed_kernel(
    const int* __restrict__ idx, const float* __restrict__ emb,
    float* __restrict__ X)
{
    int i   = blockIdx.x * 256 + threadIdx.x;
    int tok = i / (DD / 4);
    int c4  = i % (DD / 4);
    const float4* src = (const float4*)(emb + (size_t)idx[tok] * DD);
    ((float4*)X)[i] = src[c4];
}

// ---------------------------------------------------------------------------
// Rotary cos/sin table
// ---------------------------------------------------------------------------
__global__ __launch_bounds__(256) void rope_table_kernel(
    float* __restrict__ cosT, float* __restrict__ sinT)
{
    int i = blockIdx.x * 256 + threadIdx.x;
    int j = i & 31;
    int l = i >> 5;
    double inv = pow(10000.0, -(double)(2 * j) / (double)HDIM);
    double fr  = (double)l * inv;
    cosT[i] = (float)cos(fr);
    sinT[i] = (float)sin(fr);
}

// ---------------------------------------------------------------------------
// Fused phi(K) + KV contraction: per (bh, L-chunk) block.
// ---------------------------------------------------------------------------
#define PKV_AV_STR 72
#define PKV_A_STR  68
#define PKV_PS_STR 40
#define PKV_OFF_PS (128 * PKV_AV_STR)                  // 9216 floats
#define PKV_OFF_OM (PKV_OFF_PS + 128 * PKV_PS_STR)     // 14336
#define PKV_OFF_KS (PKV_OFF_OM + HDIM * PKV_PS_STR)    // 16896
#define SMEM_PKV   ((PKV_OFF_KS + 256) * 4)            // 68608 bytes

__global__ __launch_bounds__(256, 2) void phikv_kernel(
    const float* __restrict__ K, const float* __restrict__ V,
    const float* __restrict__ omega,
    const float* __restrict__ cosT, const float* __restrict__ sinT,
    const int* __restrict__ mask,
    float* __restrict__ KVP, float* __restrict__ KSP)
{
    extern __shared__ float sm[];
    float* AV  = sm;
    float* Ps  = sm + PKV_OFF_PS;
    float* Om  = sm + PKV_OFF_OM;
    float* Kss = sm + PKV_OFF_KS;

    int tid = threadIdx.x, lane = tid & 31, warp = tid >> 5;
    int bh = blockIdx.x, ch = blockIdx.y;
    int b = bh / HH, h = bh % HH;
    int lbase = ch * (LL / KVCH);

    {
        int i0 = tid * 8;
        #pragma unroll
        for (int u = 0; u < 2; u++) {
            int i = i0 + u * 4;
            float4 v = *(const float4*)(omega + i);
            int d = i >> 5, f = i & 31;
            Om[d * PKV_PS_STR + f + 0] = tf32_rna(v.x);
            Om[d * PKV_PS_STR + f + 1] = tf32_rna(v.y);
            Om[d * PKV_PS_STR + f + 2] = tf32_rna(v.z);
            Om[d * PKV_PS_STR + f + 3] = tf32_rna(v.w);
        }
    }

    float kvacc[2][4];
    #pragma unroll
    for (int i = 0; i < 2; i++)
        #pragma unroll
        for (int j = 0; j < 4; j++) kvacc[i][j] = 0.f;
    float ksacc = 0.f;

    for (int st = 0; st < 4; st++) {
        int l0 = lbase + st * 128;

        {
            int row = tid >> 1;
            int j0  = (tid & 1) * 16;
            int l   = l0 + row;
            const float* xp = K + ((size_t)(b * LL) + l) * DD + h * HDIM;
            #pragma unroll
            for (int jj = 0; jj < 4; jj++) {
                int j = j0 + jj * 4;
                float4 x1 = *(const float4*)(xp + j);
                float4 x2 = *(const float4*)(xp + j + 32);
                float4 c  = *(const float4*)(cosT + l * 32 + j);
                float4 s  = *(const float4*)(sinT + l * 32 + j);
                float* a1 = AV + row * PKV_A_STR + j;
                a1[0]  = tf32_rna(x1.x * c.x - x2.x * s.x);
                a1[32] = tf32_rna(x2.x * c.x + x1.x * s.x);
                a1[1]  = tf32_rna(x1.y * c.y - x2.y * s.y);
                a1[33] = tf32_rna(x2.y * c.y + x1.y * s.y);
                a1[2]  = tf32_rna(x1.z * c.z - x2.z * s.z);
                a1[34] = tf32_rna(x2.z * c.z + x1.z * s.z);
                a1[3]  = tf32_rna(x1.w * c.w - x2.w * s.w);
                a1[35] = tf32_rna(x2.w * c.w + x1.w * s.w);
            }
        }
        __syncthreads();

        {
            int rbase = warp * 16 + (lane >> 2);
            float p[4][4];
            #pragma unroll
            for (int i = 0; i < 4; i++)
                #pragma unroll
                for (int j = 0; j < 4; j++) p[i][j] = 0.f;
            #pragma unroll
            for (int ks = 0; ks < 8; ks++) {
                int kc = ks * 8 + (lane & 3);
                unsigned a[4];
                a[0] = __float_as_uint(AV[rbase * PKV_A_STR + kc]);
                a[1] = __float_as_uint(AV[(rbase + 8) * PKV_A_STR + kc]);
                a[2] = __float_as_uint(AV[rbase * PKV_A_STR + kc + 4]);
                a[3] = __float_as_uint(AV[(rbase + 8) * PKV_A_STR + kc + 4]);
                #pragma unroll
                for (int fn = 0; fn < 4; fn++) {
                    int cn = fn * 8 + (lane >> 2);
                    unsigned bb[2];
                    bb[0] = __float_as_uint(Om[kc * PKV_PS_STR + cn]);
                    bb[1] = __float_as_uint(Om[(kc + 4) * PKV_PS_STR + cn]);
                    mma_tf32(p[fn], a, bb);
                }
            }
            float m0 = (float)mask[b * LL + l0 + rbase];
            float m1 = (float)mask[b * LL + l0 + rbase + 8];
            #pragma unroll
            for (int fn = 0; fn < 4; fn++) {
                int cl = fn * 8 + 2 * (lane & 3);
                Ps[rbase * PKV_PS_STR + cl]           = tf32_rna(fmaxf(p[fn][0], 0.f) * m0);
                Ps[rbase * PKV_PS_STR + cl + 1]       = tf32_rna(fmaxf(p[fn][1], 0.f) * m0);
                Ps[(rbase + 8) * PKV_PS_STR + cl]     = tf32_rna(fmaxf(p[fn][2], 0.f) * m1);
                Ps[(rbase + 8) * PKV_PS_STR + cl + 1] = tf32_rna(fmaxf(p[fn][3], 0.f) * m1);
            }
        }
        __syncthreads();

        {
            int f = tid & 31, grp = tid >> 5;
            float s = 0.f;
            #pragma unroll
            for (int r = 0; r < 16; r++)
                s += Ps[(grp * 16 + r) * PKV_PS_STR + f];
            ksacc += s;
        }
        {
            int row = tid >> 1;
            int c0  = (tid & 1) * 32;
            const float* vp = V + ((size_t)(b * LL) + l0 + row) * DD + h * HDIM + c0;
            float* dst = AV + row * PKV_AV_STR + c0;
            #pragma unroll
            for (int i = 0; i < 8; i++) {
                float4 v = *(const float4*)(vp + i * 4);
                dst[i * 4 + 0] = tf32_rna(v.x);
                dst[i * 4 + 1] = tf32_rna(v.y);
                dst[i * 4 + 2] = tf32_rna(v.z);
                dst[i * 4 + 3] = tf32_rna(v.w);
            }
        }
        __syncthreads();

        {
            int cn = warp * 8 + (lane >> 2);
            #pragma unroll
            for (int ks = 0; ks < 16; ks++) {
                int kc = ks * 8 + (lane & 3);
                unsigned bb[2];
                bb[0] = __float_as_uint(AV[kc * PKV_AV_STR + cn]);
                bb[1] = __float_as_uint(AV[(kc + 4) * PKV_AV_STR + cn]);
                #pragma unroll
                for (int fm = 0; fm < 2; fm++) {
                    int r = fm * 16 + (lane >> 2);
                    unsigned a[4];
                    a[0] = __float_as_uint(Ps[kc * PKV_PS_STR + r]);
                    a[1] = __float_as_uint(Ps[kc * PKV_PS_STR + r + 8]);
                    a[2] = __float_as_uint(Ps[(kc + 4) * PKV_PS_STR + r]);
                    a[3] = __float_as_uint(Ps[(kc + 4) * PKV_PS_STR + r + 8]);
                    mma_tf32(kvacc[fm], a, bb);
                }
            }
        }
        __syncthreads();
    }

    {
        size_t base = ((size_t)(ch * NBH + bh)) * FDIM * HDIM;
        #pragma unroll
        for (int fm = 0; fm < 2; fm++) {
            int f0 = fm * 16 + (lane >> 2);
            int d0 = warp * 8 + 2 * (lane & 3);
            *(float2*)(KVP + base + (size_t)f0 * HDIM + d0) =
                make_float2(kvacc[fm][0], kvacc[fm][1]);
            *(float2*)(KVP + base + (size_t)(f0 + 8) * HDIM + d0) =
                make_float2(kvacc[fm][2], kvacc[fm][3]);
        }
    }
    Kss[tid] = ksacc;
    __syncthreads();
    if (tid < FDIM) {
        float s = 0.f;
        #pragma unroll
        for (int g = 0; g < 8; g++) s += Kss[g * 32 + tid];
        KSP[(size_t)(ch * NBH + bh) * FDIM + tid] = s;
    }
}

// ---------------------------------------------------------------------------
// Fused attention output: Y = (relu(rot(Q)@omega) @ KV) * z
// ---------------------------------------------------------------------------
#define PHI_A_STR 68
#define PHI_B_STR 40
#define AT_KV_STR 72
#define AT_OFF_PS  (128 * PHI_A_STR)
#define AT_OFF_OM  (AT_OFF_PS + 128 * PHI_B_STR)
#define AT_OFF_KV  (AT_OFF_OM + HDIM * PHI_B_STR)
#define AT_OFF_DEN (AT_OFF_KV + FDIM * AT_KV_STR)
#define AT_OFF_KSM (AT_OFF_DEN + 128)
#define SMEM_ATT   ((AT_OFF_KSM + FDIM) * 4)          // 75392 bytes

__global__ __launch_bounds__(256, 2) void attn_fused_kernel(
    const float* __restrict__ Q, const float* __restrict__ omega,
    const float* __restrict__ cosT, const float* __restrict__ sinT,
    const float* __restrict__ KVP, const float* __restrict__ KSP,
    float* __restrict__ Y)
{
    extern __shared__ float sm[];
    float* As  = sm;
    float* Ps  = sm + AT_OFF_PS;
    float* Om  = sm + AT_OFF_OM;
    float* Kv  = sm + AT_OFF_KV;
    float* Den = sm + AT_OFF_DEN;
    float* Ksm = sm + AT_OFF_KSM;

    int tid = threadIdx.x, lane = tid & 31, warp = tid >> 5;
    int bh = blockIdx.y;
    int b  = bh / HH, h = bh % HH;
    int tok0 = blockIdx.x * 128;

    {
        int i0 = tid * 8;
        #pragma unroll
        for (int u = 0; u < 2; u++) {
            int i = i0 + u * 4;
            float4 v = *(const float4*)(omega + i);
            int d = i >> 5, f = i & 31;
            Om[d * PHI_B_STR + f + 0] = tf32_rna(v.x);
            Om[d * PHI_B_STR + f + 1] = tf32_rna(v.y);
            Om[d * PHI_B_STR + f + 2] = tf32_rna(v.z);
            Om[d * PHI_B_STR + f + 3] = tf32_rna(v.w);
        }
    }
    {
        const float* kv0 = KVP + (size_t)bh * FDIM * HDIM;
        int i0 = tid * 8;
        #pragma unroll
        for (int u = 0; u < 2; u++) {
            int i = i0 + u * 4;
            float4 v0 = *(const float4*)(kv0 + i);
            float4 v1 = *(const float4*)(kv0 + NKV + i);
            float4 v2 = *(const float4*)(kv0 + 2 * (size_t)NKV + i);
            float4 v3 = *(const float4*)(kv0 + 3 * (size_t)NKV + i);
            float4 v;
            v.x = v0.x + v1.x + v2.x + v3.x;
            v.y = v0.y + v1.y + v2.y + v3.y;
            v.z = v0.z + v1.z + v2.z + v3.z;
            v.w = v0.w + v1.w + v2.w + v3.w;
            int f = i >> 6, d = i & 63;
            *(float4*)&Kv[f * AT_KV_STR + d] = v;
        }
    }
    if (tid < FDIM) {
        int i = bh * FDIM + tid;
        Ksm[tid] = KSP[i] + KSP[NKS + i] + KSP[2 * NKS + i] + KSP[3 * NKS + i];
    }

    {
        int row = tid >> 1;
        int j0  = (tid & 1) * 16;
        int l   = tok0 + row;
        const float* xp = Q + ((size_t)(b * LL) + l) * DD + h * HDIM;
        #pragma unroll
        for (int jj = 0; jj < 4; jj++) {
            int j = j0 + jj * 4;
            float4 x1 = *(const float4*)(xp + j);
            float4 x2 = *(const float4*)(xp + j + 32);
            float4 c  = *(const float4*)(cosT + l * 32 + j);
            float4 s  = *(const float4*)(sinT + l * 32 + j);
            float* a1 = As + row * PHI_A_STR + j;
            a1[0]  = tf32_rna(x1.x * c.x - x2.x * s.x);
            a1[32] = tf32_rna(x2.x * c.x + x1.x * s.x);
            a1[1]  = tf32_rna(x1.y * c.y - x2.y * s.y);
            a1[33] = tf32_rna(x2.y * c.y + x1.y * s.y);
            a1[2]  = tf32_rna(x1.z * c.z - x2.z * s.z);
            a1[34] = tf32_rna(x2.z * c.z + x1.z * s.z);
            a1[3]  = tf32_rna(x1.w * c.w - x2.w * s.w);
            a1[35] = tf32_rna(x2.w * c.w + x1.w * s.w);
        }
    }
    __syncthreads();

    int rbase = warp * 16 + (lane >> 2);

    {
        float p[4][4];
        #pragma unroll
        for (int i = 0; i < 4; i++)
            #pragma unroll
            for (int j = 0; j < 4; j++) p[i][j] = 0.f;
        #pragma unroll
        for (int ks = 0; ks < 8; ks++) {
            int kc = ks * 8 + (lane & 3);
            unsigned a[4];
            a[0] = __float_as_uint(As[rbase * PHI_A_STR + kc]);
            a[1] = __float_as_uint(As[(rbase + 8) * PHI_A_STR + kc]);
            a[2] = __float_as_uint(As[rbase * PHI_A_STR + kc + 4]);
            a[3] = __float_as_uint(As[(rbase + 8) * PHI_A_STR + kc + 4]);
            #pragma unroll
            for (int fn = 0; fn < 4; fn++) {
                int cn = fn * 8 + (lane >> 2);
                unsigned bb[2];
                bb[0] = __float_as_uint(Om[kc * PHI_B_STR + cn]);
                bb[1] = __float_as_uint(Om[(kc + 4) * PHI_B_STR + cn]);
                mma_tf32(p[fn], a, bb);
            }
        }
        #pragma unroll
        for (int fn = 0; fn < 4; fn++) {
            int cl = fn * 8 + 2 * (lane & 3);
            Ps[rbase * PHI_B_STR + cl]           = fmaxf(p[fn][0], 0.f);
            Ps[rbase * PHI_B_STR + cl + 1]       = fmaxf(p[fn][1], 0.f);
            Ps[(rbase + 8) * PHI_B_STR + cl]     = fmaxf(p[fn][2], 0.f);
            Ps[(rbase + 8) * PHI_B_STR + cl + 1] = fmaxf(p[fn][3], 0.f);
        }
    }
    __syncthreads();

    if (tid < 128) {
        float s = ATTN_EPS;
        #pragma unroll
        for (int f = 0; f < FDIM; f++) s += Ps[tid * PHI_B_STR + f] * Ksm[f];
        Den[tid] = 1.0f / s;
    }
    __syncthreads();

    float o[8][4];
    #pragma unroll
    for (int i = 0; i < 8; i++)
        #pragma unroll
        for (int j = 0; j < 4; j++) o[i][j] = 0.f;
    #pragma unroll
    for (int ks = 0; ks < 4; ks++) {
        int kc = ks * 8 + (lane & 3);
        unsigned a[4];
        a[0] = __float_as_uint(Ps[rbase * PHI_B_STR + kc]);
        a[1] = __float_as_uint(Ps[(rbase + 8) * PHI_B_STR + kc]);
        a[2] = __float_as_uint(Ps[rbase * PHI_B_STR + kc + 4]);
        a[3] = __float_as_uint(Ps[(rbase + 8) * PHI_B_STR + kc + 4]);
        #pragma unroll
        for (int fn = 0; fn < 8; fn++) {
            int cn = fn * 8 + (lane >> 2);
            unsigned bb[2];
            bb[0] = __float_as_uint(Kv[kc * AT_KV_STR + cn]);
            bb[1] = __float_as_uint(Kv[(kc + 4) * AT_KV_STR + cn]);
            mma_tf32(o[fn], a, bb);
        }
    }

    float z0 = Den[rbase];
    float z1 = Den[rbase + 8];
    size_t t0 = (size_t)(b * LL + tok0) + rbase;
    float* y0 = Y + t0 * DD + h * HDIM;
    float* y1 = Y + (t0 + 8) * DD + h * HDIM;
    #pragma unroll
    for (int fn = 0; fn < 8; fn++) {
        int cl = fn * 8 + 2 * (lane & 3);
        *(float2*)(y0 + cl) = make_float2(o[fn][0] * z0, o[fn][1] * z0);
        *(float2*)(y1 + cl) = make_float2(o[fn][2] * z1, o[fn][3] * z1);
    }
}

// ---------------------------------------------------------------------------
// Warp-per-row LayerNorm
// ---------------------------------------------------------------------------
__global__ __launch_bounds__(256) void ln_kernel(
    const float* __restrict__ in, const float* __restrict__ g,
    const float* __restrict__ b, float* __restrict__ out)
{
    int warp = threadIdx.x >> 5, lane = threadIdx.x & 31;
    size_t row = (size_t)blockIdx.x * 8 + warp;
    const float4* ip = (const float4*)(in + row * DD);

    float4 x[6];
    float s = 0.f, s2 = 0.f;
    #pragma unroll
    for (int i = 0; i < 6; i++) {
        x[i] = ip[lane + i * 32];
        s  += x[i].x + x[i].y + x[i].z + x[i].w;
        s2 += x[i].x * x[i].x + x[i].y * x[i].y
            + x[i].z * x[i].z + x[i].w * x[i].w;
    }
    #pragma unroll
    for (int off = 16; off > 0; off >>= 1) {
        s  += __shfl_xor_sync(0xFFFFFFFF, s,  off);
        s2 += __shfl_xor_sync(0xFFFFFFFF, s2, off);
    }
    float mu   = s * (1.0f / DD);
    float rstd = rsqrtf(s2 * (1.0f / DD) - mu * mu + LN_EPS);

    const float4* gp = (const float4*)g;
    const float4* bp = (const float4*)b;
    float4* op = (float4*)(out + row * DD);
    #pragma unroll
    for (int i = 0; i < 6; i++) {
        float4 gg = gp[lane + i * 32];
        float4 bb = bp[lane + i * 32];
        float4 o;
        o.x = (x[i].x - mu) * rstd * gg.x + bb.x;
        o.y = (x[i].y - mu) * rstd * gg.y + bb.y;
        o.z = (x[i].z - mu) * rstd * gg.z + bb.z;
        o.w = (x[i].w - mu) * rstd * gg.w + bb.w;
        op[lane + i * 32] = o;
    }
}

// ---------------------------------------------------------------------------
// Host orchestration
// ---------------------------------------------------------------------------
extern "C" void kernel_launch(void* const* d_in, const int* in_sizes, int n_in,
                              void* d_out, int out_size)
{
    const int*   idx     = (const int*)  d_in[0];
    const int*   mask    = (const int*)  d_in[1];
    const float* tok_emb = (const float*)d_in[2];
    const float* Wq = (const float*)d_in[3];
    const float* bq = (const float*)d_in[4];
    const float* Wk = (const float*)d_in[5];
    const float* bk = (const float*)d_in[6];
    const float* Wv = (const float*)d_in[7];
    const float* bv = (const float*)d_in[8];
    const float* Wo = (const float*)d_in[9];
    const float* bo = (const float*)d_in[10];
    const float* om = (const float*)d_in[11];
    const float* W1 = (const float*)d_in[12];
    const float* b1 = (const float*)d_in[13];
    const float* W2 = (const float*)d_in[14];
    const float* b2 = (const float*)d_in[15];
    const float* g1 = (const float*)d_in[16];
    const float* be1= (const float*)d_in[17];
    const float* g2 = (const float*)d_in[18];
    const float* be2= (const float*)d_in[19];
    const float* gf = (const float*)d_in[20];
    const float* bf = (const float*)d_in[21];
    float* out = (float*)d_out;

    float *X, *Y, *Q, *K, *V, *KVP, *KSP, *COS, *SIN;
    cudaGetSymbolAddress((void**)&X,    g_X);
    cudaGetSymbolAddress((void**)&Y,    g_Y);
    cudaGetSymbolAddress((void**)&Q,    g_Q);
    cudaGetSymbolAddress((void**)&K,    g_K);
    cudaGetSymbolAddress((void**)&V,    g_V);
    cudaGetSymbolAddress((void**)&KVP,  g_KVP);
    cudaGetSymbolAddress((void**)&KSP,  g_KSP);
    cudaGetSymbolAddress((void**)&COS,  g_COS);
    cudaGetSymbolAddress((void**)&SIN,  g_SIN);

    cudaFuncSetAttribute(pgemm_kernel,
                         cudaFuncAttributeMaxDynamicSharedMemorySize, SMEM_GEMM);
    cudaFuncSetAttribute(qkv_gemm_kernel,
                         cudaFuncAttributeMaxDynamicSharedMemorySize, SMEM_GEMM);
    cudaFuncSetAttribute(phikv_kernel,
                         cudaFuncAttributeMaxDynamicSharedMemorySize, SMEM_PKV);
    cudaFuncSetAttribute(attn_fused_kernel,
                         cudaFuncAttributeMaxDynamicSharedMemorySize, SMEM_ATT);

    const size_t WMAT = (size_t)DD * DD;
    dim3 gGrid(DD / TN, NTOK / TM);       // (6, 256)
    dim3 qkvGrid(3 * DD / TN, NTOK / TM); // (18, 256)
    dim3 attGrid(LL / 128, NBH);          // (16, 192)

    rope_table_kernel<<<(LL * 32) / 256, 256>>>(COS, SIN);
    embed_kernel<<<(NTOK * DD / 4) / 256, 256>>>(idx, tok_emb, X);

    for (int i = 0; i < NLAYER; i++) {
        const float* om_i = om + (size_t)i * HDIM * FDIM;

        qkv_gemm_kernel<<<qkvGrid, 256, SMEM_GEMM>>>(
            X, Wq + i * WMAT, Wk + i * WMAT, Wv + i * WMAT,
            bq + i * DD, bk + i * DD, bv + i * DD, Q, K, V);

        phikv_kernel<<<dim3(NBH, KVCH), 256, SMEM_PKV>>>(
            K, V, om_i, COS, SIN, mask, KVP, KSP);

        attn_fused_kernel<<<attGrid, 256, SMEM_ATT>>>(
            Q, om_i, COS, SIN, KVP, KSP, Y);

        // X = Y @ Wo + bo + X
        pgemm_kernel<<<gGrid, 256, SMEM_GEMM>>>(Y, Wo + i * WMAT, bo + i * DD, X, X, 0);
        ln_kernel<<<NTOK / 8, 256>>>(X, g1 + i * DD, be1 + i * DD, X);
        // Q = gelu(X @ W1 + b1)
        pgemm_kernel<<<gGrid, 256, SMEM_GEMM>>>(X, W1 + i * WMAT, b1 + i * DD, nullptr, Q, 1);
        // Y = Q @ W2 + b2 + X
        pgemm_kernel<<<gGrid, 256, SMEM_GEMM>>>(Q, W2 + i * WMAT, b2 + i * DD, X, Y, 0);
        ln_kernel<<<NTOK / 8, 256>>>(Y, g2 + i * DD, be2 + i * DD, X);
    }

    ln_kernel<<<NTOK / 8, 256>>>(X, gf, bf, out);
}